// round 14
// baseline (speedup 1.0000x reference)
#include <cuda_runtime.h>
#include <cuda_fp16.h>
#include <math.h>
#include <stdint.h>

namespace {
constexpr int kB = 2, kS = 1024, kE = 1024, kH = 16, kD = 64, kF = 4096, kV = 32000;
constexpr int kBS = kB * kS, kBH = kB * kH, kQKV = 3 * kE;
}

// ------------------------- device scratch -------------------------
__device__ float  g_emb [kBS * kE];
__device__ float  g_qkv [kBS * kQKV];
__device__ float  g_sc  [(size_t)kBH * kS * kS];
__device__ float  g_ct  [kS * kD];
__device__ float  g_st  [kS * kD];

__device__ __half g_eh[kBS*kE], g_el[kBS*kE];
__device__ __half g_wqkvh[kQKV*kE];
__device__ __half g_qh[kBH*kS*kD], g_ql[kBH*kS*kD];
__device__ __half g_kh[kBH*kS*kD], g_kl[kBH*kS*kD];
__device__ __half g_vth[kBH*kD*kS], g_vtl[kBH*kD*kS];
__device__ __half g_ph[(size_t)kBH*kS*kS], g_pl[(size_t)kBH*kS*kS];
__device__ __half g_o2h[kBS*kE], g_o2l[kBS*kE];
__device__ __half g_wph[kE*kE],  g_wpl[kE*kE];
__device__ __half g_wuh[kF*kE];
__device__ __half g_wgh[kF*kE];
__device__ __half g_wdh[kE*kF];
__device__ __half g_hh[kBS*kE],  g_hl[kBS*kE];
__device__ __half g_uh0[kBS*kF], g_ul0[kBS*kF];
__device__ __half g_gh0[kBS*kF], g_gl0[kBS*kF];
__device__ __half g_uh[kBS*kF],  g_ul[kBS*kF];
__device__ __half g_pwh[(size_t)kV*kE];

// ------------------------- PTX helpers -------------------------
__device__ __forceinline__ uint32_t smem_u32(const void* p) {
    uint32_t a;
    asm("{ .reg .u64 t; cvta.to.shared.u64 t, %1; cvt.u32.u64 %0, t; }" : "=r"(a) : "l"(p));
    return a;
}
__device__ __forceinline__ void cpasync16(uint32_t dst, const void* src) {
    asm volatile("cp.async.cg.shared.global [%0], [%1], 16;" :: "r"(dst), "l"(src));
}
#define CP_COMMIT() asm volatile("cp.async.commit_group;" ::: "memory")
#define CP_WAIT0()  asm volatile("cp.async.wait_group 0;" ::: "memory")

__device__ __forceinline__ void ldsm4(uint32_t* r, uint32_t addr) {
    asm volatile("ldmatrix.sync.aligned.m8n8.x4.shared.b16 {%0,%1,%2,%3}, [%4];"
        : "=r"(r[0]), "=r"(r[1]), "=r"(r[2]), "=r"(r[3]) : "r"(addr));
}
__device__ __forceinline__ void hmma(float* c, const uint32_t* a, const uint32_t* b) {
    asm volatile("mma.sync.aligned.m16n8k16.row.col.f32.f16.f16.f32 "
        "{%0,%1,%2,%3}, {%4,%5,%6,%7}, {%8,%9}, {%0,%1,%2,%3};"
        : "+f"(c[0]), "+f"(c[1]), "+f"(c[2]), "+f"(c[3])
        : "r"(a[0]), "r"(a[1]), "r"(a[2]), "r"(a[3]), "r"(b[0]), "r"(b[1]));
}
__device__ __forceinline__ void hmma16(uint32_t* c, const uint32_t* a, const uint32_t* b) {
    asm volatile("mma.sync.aligned.m16n8k16.row.col.f16.f16.f16.f16 "
        "{%0,%1}, {%2,%3,%4,%5}, {%6,%7}, {%0,%1};"
        : "+r"(c[0]), "+r"(c[1])
        : "r"(a[0]), "r"(a[1]), "r"(a[2]), "r"(a[3]), "r"(b[0]), "r"(b[1]));
}
__device__ __forceinline__ void split2(float v, __half* h, __half* l) {
    __half hi = __float2half(v);
    *h = hi;
    *l = __float2half((v - __half2float(hi)) * 1024.f);
}

// stage one ROWS x 64 fp16 tile into 176B-padded smem rows (conflict-free ldsm)
template<int ROWS, int TPB>
__device__ __forceinline__ void stage_cp(uint32_t dst, const __half* __restrict__ src,
                                         long long ld, int k0, int tid)
{
#pragma unroll
    for (int it = 0; it < ROWS * 8 / TPB; it++) {
        int i = it * TPB + tid;
        int r = i >> 3, c = i & 7;
        cpasync16(dst + r * 176 + c * 16, src + (long long)r * ld + k0 + c * 8);
    }
}

// ------------------------- HMMA GEMM -------------------------
// C = alpha * (A @ B^T) (+bias) (+C).
// MODE 2: full hi/lo split (3 MMAs). MODE 1: A split, B hi (2 MMAs).
// MODE 0: plain fp16, fp32 acc (1 MMA).
// OUT 0: fp32 C.  OUT 1: split hi/lo -> Ch/Cl.  OUT 2: fp32 C (+ACCUM) AND Ch/Cl.
// OUT 3: split hi/lo at attention map [(b,h),s,d] -> ((b*kS+s)<<10)+(h<<6)+d.
// BM=128, BK=64, 256 thr (8 warps, 64x32 warp tiles for BN=128),
// 2-stage cp.async, explicit fragment double-buffering (LDSM/HMMA overlap).
// CAUSAL: skip tiles above diagonal. CAUSK: clamp K at (by+1)*128.
template<int BN, int MODE, int OUT, bool ACCUM, bool BIAS, bool CAUSAL, bool CAUSK>
__global__ void __launch_bounds__(256, 1)
tgemm_k(const __half* __restrict__ Ah, const __half* __restrict__ Al, int lda, long long sA,
        const __half* __restrict__ Bh, const __half* __restrict__ Bl, int ldb, long long sB,
        float* __restrict__ C, __half* __restrict__ Ch, __half* __restrict__ Cl,
        int ldc, long long sC,
        const float* __restrict__ bias, float alpha, int K)
{
    constexpr int BM = 128, BK = 64, TPB = 256;
    constexpr int WN = (BN == 128) ? 4 : 2;
    constexpr int WM = 8 / WN;
    constexpr int MT = BM / (WM * 16);           // 4 (BN=128) / 2 (BN=64)
    constexpr int NT = BN / (WN * 8);            // 4
    constexpr int TILEA = BM * 176;
    constexpr int TILEB = BN * 176;
    constexpr int NA = (MODE >= 1) ? 2 : 1;
    constexpr int NB = (MODE == 2) ? 2 : 1;
    constexpr int STAGE = NA * TILEA + NB * TILEB;

    const int bx = blockIdx.x, by = blockIdx.y, bz = blockIdx.z;
    if (CAUSAL && bx * BN > by * BM + BM - 1) return;
    int Ktot = K;
    if (CAUSK) { int km = (by + 1) * BM; if (km < Ktot) Ktot = km; }
    const int NC = Ktot / BK;

    extern __shared__ char sm[];
    const uint32_t sb = smem_u32(sm);
    const int tid = threadIdx.x, lane = tid & 31, wid = tid >> 5;
    const int m0 = (wid / WN) * MT * 16;
    const int n0 = (wid % WN) * NT * 8;

    const __half* pAh = Ah + bz * sA + (long long)by * BM * lda;
    const __half* pAl = (MODE >= 1) ? Al + bz * sA + (long long)by * BM * lda : nullptr;
    const __half* pBh = Bh + bz * sB + (long long)bx * BN * ldb;
    const __half* pBl = (MODE == 2) ? Bl + bz * sB + (long long)bx * BN * ldb : nullptr;

    float    acc1[MT][NT][4];
    uint32_t acc2[MT][NT][2];
#pragma unroll
    for (int mt = 0; mt < MT; mt++)
#pragma unroll
        for (int nt = 0; nt < NT; nt++) {
#pragma unroll
            for (int i = 0; i < 4; i++) acc1[mt][nt][i] = 0.f;
            acc2[mt][nt][0] = 0u; acc2[mt][nt][1] = 0u;
        }

    auto stage_all = [&](int buf, int k0) {
        uint32_t s0 = sb + (uint32_t)buf * STAGE;
        stage_cp<BM, TPB>(s0, pAh, lda, k0, tid);
        stage_cp<BN, TPB>(s0 + NA*TILEA, pBh, ldb, k0, tid);
        if (MODE >= 1) stage_cp<BM, TPB>(s0 + TILEA, pAl, lda, k0, tid);
        if (MODE == 2) stage_cp<BN, TPB>(s0 + NA*TILEA + TILEB, pBl, ldb, k0, tid);
    };

    stage_all(0, 0); CP_COMMIT();

    // double-buffered fragments
    uint32_t ahf[2][MT][4], alf[2][MT][4], bhf[2][NT][2], blf[2][NT][2];

    for (int i = 0; i < NC; i++) {
        CP_WAIT0();
        __syncthreads();
        if (i + 1 < NC) { stage_all((i + 1) & 1, (i + 1) * BK); CP_COMMIT(); }

        const uint32_t s0 = sb + (uint32_t)(i & 1) * STAGE;
        const uint32_t aH = s0, aL = s0 + TILEA;
        const uint32_t bH = s0 + NA*TILEA, bL = s0 + NA*TILEA + TILEB;

        auto load_frags = [&](int ks, int fb) {
            const int kc = ks * 2;
#pragma unroll
            for (int nt = 0; nt < NT; nt += 2) {
                const int g = lane >> 3;
                const uint32_t off =
                    (uint32_t)(n0 + nt * 8 + ((g >> 1) << 3) + (lane & 7)) * 176
                    + (uint32_t)(kc + (g & 1)) * 16;
                uint32_t r[4];
                ldsm4(r, bH + off);
                bhf[fb][nt][0] = r[0]; bhf[fb][nt][1] = r[1];
                bhf[fb][nt+1][0] = r[2]; bhf[fb][nt+1][1] = r[3];
                if (MODE == 2) {
                    ldsm4(r, bL + off);
                    blf[fb][nt][0] = r[0]; blf[fb][nt][1] = r[1];
                    blf[fb][nt+1][0] = r[2]; blf[fb][nt+1][1] = r[3];
                }
            }
#pragma unroll
            for (int mt = 0; mt < MT; mt++) {
                const uint32_t off =
                    (uint32_t)(m0 + mt * 16 + (lane & 15)) * 176
                    + (uint32_t)(kc + (lane >> 4)) * 16;
                ldsm4(ahf[fb][mt], aH + off);
                if (MODE >= 1) ldsm4(alf[fb][mt], aL + off);
            }
        };

        load_frags(0, 0);
#pragma unroll
        for (int ks = 0; ks < 4; ks++) {
            const int fb = ks & 1;
            if (ks < 3) load_frags(ks + 1, fb ^ 1);
#pragma unroll
            for (int mt = 0; mt < MT; mt++)
#pragma unroll
                for (int nt = 0; nt < NT; nt++) {
                    hmma(acc1[mt][nt], ahf[fb][mt], bhf[fb][nt]);
                    if (MODE == 2) hmma16(acc2[mt][nt], ahf[fb][mt], blf[fb][nt]);
                    if (MODE >= 1) hmma16(acc2[mt][nt], alf[fb][mt], bhf[fb][nt]);
                }
        }
    }

    // ---- epilogue ----
    const float inv = 1.f / 1024.f;
#pragma unroll
    for (int mt = 0; mt < MT; mt++) {
#pragma unroll
        for (int nt = 0; nt < NT; nt++) {
            const int row = by * BM + m0 + mt * 16 + (lane >> 2);
            const int col = bx * BN + n0 + nt * 8 + ((lane & 3) << 1);
#pragma unroll
            for (int h = 0; h < 2; h++) {
                const int r = row + h * 8;
                float v0 = acc1[mt][nt][2*h], v1 = acc1[mt][nt][2*h+1];
                if (MODE >= 1) {
                    __half2 c2 = *reinterpret_cast<__half2*>(&acc2[mt][nt][h]);
                    v0 += __low2float(c2) * inv;
                    v1 += __high2float(c2) * inv;
                }
                v0 *= alpha; v1 *= alpha;
                if (BIAS) { v0 += bias[col]; v1 += bias[col + 1]; }

                if (OUT == 0 || OUT == 2) {
                    float* Cp = C + bz * sC + (long long)r * ldc + col;
                    float a0 = v0, a1 = v1;
                    if (ACCUM) { float2 o = *reinterpret_cast<float2*>(Cp); a0 += o.x; a1 += o.y; }
                    *reinterpret_cast<float2*>(Cp) = make_float2(a0, a1);
                    if (OUT == 2) { v0 = a0; v1 = a1; }
                }
                if (OUT >= 1) {
                    size_t idx;
                    if (OUT == 3) {
                        int bb = bz >> 4, hh = bz & 15;
                        idx = (((size_t)(bb * kS + r)) << 10) + (hh << 6) + col;
                    } else {
                        idx = (size_t)bz * sC + (size_t)r * ldc + col;
                    }
                    __half h0, l0, h1, l1;
                    split2(v0, &h0, &l0);
                    split2(v1, &h1, &l1);
                    *reinterpret_cast<__half2*>(Ch + idx) = __halves2half2(h0, h1);
                    *reinterpret_cast<__half2*>(Cl + idx) = __halves2half2(l0, l1);
                }
            }
        }
    }
}

// ------------------------- elementwise kernels -------------------------
__global__ void embed_k(const int* __restrict__ tok, const float* __restrict__ tab,
                        float* __restrict__ out, __half* __restrict__ eh, __half* __restrict__ el)
{
    int idx = blockIdx.x * blockDim.x + threadIdx.x;
    float v = tab[(size_t)tok[idx >> 10] * kE + (idx & 1023)];
    out[idx] = v; split2(v, eh + idx, el + idx);
}

__global__ void costab_k(float* __restrict__ ct, float* __restrict__ st)
{
    int idx = blockIdx.x * blockDim.x + threadIdx.x;
    int s = idx / kD, i = idx % kD;
    float theta = powf(10000.f, (-2.f / kD) * (float)(i & 31));
    ct[idx] = cosf((float)s * theta);
    st[idx] = sinf((float)s * theta) * (i < kD/2 ? -1.f : 1.f);
}

// fused qkv weights -> [3*H*D, E] fp16 hi only
__global__ void wqkv_k(const float* __restrict__ wq, const float* __restrict__ wk,
                       const float* __restrict__ wv, __half* __restrict__ h)
{
    int idx = blockIdx.x * blockDim.x + threadIdx.x;
    int n = idx / kE, e = idx % kE;
    int seg = n >> 10, hh = (n & 1023) >> 6, k = n & 63;
    const float* w = seg == 0 ? wq : seg == 1 ? wk : wv;
    h[idx] = __float2half(w[((size_t)hh * kE + e) * kD + k]);
}

// src [K,N] fp32 -> dst [N,K] fp16 hi (and lo if dl != nullptr)
__global__ void wtr_k(const float* __restrict__ src, __half* __restrict__ dh,
                      __half* __restrict__ dl, int K, int N)
{
    __shared__ float t[32][33];
    int k0 = blockIdx.y * 32, n0 = blockIdx.x * 32;
    for (int r = threadIdx.y; r < 32; r += 8)
        t[r][threadIdx.x] = src[(size_t)(k0 + r) * N + n0 + threadIdx.x];
    __syncthreads();
    for (int r = threadIdx.y; r < 32; r += 8) {
        size_t o = (size_t)(n0 + r) * K + k0 + threadIdx.x;
        float v = t[threadIdx.x][r];
        if (dl) split2(v, dh + o, dl + o);
        else    dh[o] = __float2half(v);
    }
}

__global__ void rope_k(const float* __restrict__ qkv, const float* __restrict__ ct,
                       const float* __restrict__ st,
                       __half* __restrict__ qh, __half* __restrict__ ql,
                       __half* __restrict__ kh, __half* __restrict__ kl,
                       __half* __restrict__ vth, __half* __restrict__ vtl)
{
    int idx = blockIdx.x * blockDim.x + threadIdx.x;
    int row = idx / kQKV, c = idx % kQKV;
    int b = row >> 10, s = row & 1023;
    int seg = c >> 10, h = (c & 1023) >> 6, i = c & 63;
    float x = qkv[idx];
    if (seg == 2) {
        size_t dst = ((size_t)(b * kH + h) * kD + i) * kS + s;
        split2(x, vth + dst, vtl + dst);
        return;
    }
    float sw = qkv[(size_t)row * kQKV + (seg << 10) + (h << 6) + ((i + 32) & 63)];
    float val = ct[(s << 6) + i] * x + st[(s << 6) + i] * sw;
    size_t dst = ((size_t)(b * kH + h) * kS + s) * kD + i;
    if (seg == 0) split2(val, qh + dst, ql + dst);
    else          split2(val, kh + dst, kl + dst);
}

// register-resident causal softmax; writes only cols < kend (PV clamps K there)
__global__ void softmax_k(const float* __restrict__ sc,
                          __half* __restrict__ ph, __half* __restrict__ pl)
{
    const int r = blockIdx.x, s = r & (kS - 1), n = s + 1, t = threadIdx.x;
    const int kend = ((s >> 7) + 1) << 7;
    const float* row = sc + (size_t)r * kS;
    __half* prh = ph + (size_t)r * kS;
    __half* prl = pl + (size_t)r * kS;
    __shared__ float red[256];

    float v[4];
#pragma unroll
    for (int j = 0; j < 4; j++) {
        int i = t + j * 256;
        v[j] = (i < n) ? row[i] : -INFINITY;
    }
    float m = fmaxf(fmaxf(v[0], v[1]), fmaxf(v[2], v[3]));
    red[t] = m; __syncthreads();
    for (int o = 128; o > 0; o >>= 1) { if (t < o) red[t] = fmaxf(red[t], red[t+o]); __syncthreads(); }
    m = red[0]; __syncthreads();

    float e[4], sum = 0.f;
#pragma unroll
    for (int j = 0; j < 4; j++) {
        int i = t + j * 256;
        e[j] = (i < n) ? expf(v[j] - m) : 0.f;
        sum += e[j];
    }
    red[t] = sum; __syncthreads();
    for (int o = 128; o > 0; o >>= 1) { if (t < o) red[t] += red[t+o]; __syncthreads(); }
    float inv = 1.f / red[0];
#pragma unroll
    for (int j = 0; j < 4; j++) {
        int i = t + j * 256;
        if (i < kend) split2(e[j] * inv, prh + i, prl + i);
    }
}

__global__ void rmsnorm_k(const float* __restrict__ x, const float* __restrict__ w,
                          __half* __restrict__ yh, __half* __restrict__ yl)
{
    const int r = blockIdx.x, t = threadIdx.x;
    const float* xr = x + (size_t)r * kE;
    __shared__ float red[256];
    float sum = 0.f;
    for (int i = t; i < kE; i += 256) { float v = xr[i]; sum += v * v; }
    red[t] = sum; __syncthreads();
    for (int o = 128; o > 0; o >>= 1) { if (t < o) red[t] += red[t+o]; __syncthreads(); }
    float rs = rsqrtf(red[0] / kE + 1.1920929e-7f);
    for (int i = t; i < kE; i += 256) {
        size_t o = (size_t)r * kE + i;
        split2(xr[i] * rs * w[i], yh + o, yl + o);
    }
}

// u = (uh0+ul0/1024) * elu(gh0+gl0/1024), re-split to uh/ul
__global__ void elumul_k(const __half* __restrict__ uh0, const __half* __restrict__ ul0,
                         const __half* __restrict__ gh0, const __half* __restrict__ gl0,
                         __half* __restrict__ uh, __half* __restrict__ ul)
{
    int i = blockIdx.x * blockDim.x + threadIdx.x;
    float u = __half2float(uh0[i]) + __half2float(ul0[i]) * (1.f/1024.f);
    float g = __half2float(gh0[i]) + __half2float(gl0[i]) * (1.f/1024.f);
    float e = g > 0.f ? g : expm1f(g);
    split2(u * e, uh + i, ul + i);
}

// ------------------------- host launcher -------------------------
#define SYM(p, s) cudaGetSymbolAddress((void**)&p, s)

extern "C" void kernel_launch(void* const* d_in, const int* in_sizes, int n_in,
                              void* d_out, int out_size)
{
    (void)in_sizes; (void)n_in; (void)out_size;
    const int*   tokens = (const int*)  d_in[0];
    const float* table = (const float*)d_in[1];
    const float *Wq = (const float*)d_in[2], *Wk = (const float*)d_in[3], *Wv = (const float*)d_in[4];
    const float *Wproj = (const float*)d_in[5], *normw = (const float*)d_in[6];
    const float *Wup = (const float*)d_in[7], *Wgate = (const float*)d_in[8], *Wdown = (const float*)d_in[9];
    const float *predW = (const float*)d_in[10], *predB = (const float*)d_in[11];
    float* logits = (float*)d_out;

    float *emb, *qkv, *sc, *ct, *st;
    __half *eh, *el, *wqkvh, *qh, *ql, *kh, *kl, *vth, *vtl, *ph, *pl;
    __half *o2h, *o2l, *wph, *wpl, *wuh, *wgh, *wdh, *hh, *hl;
    __half *uh0, *ul0, *gh0, *gl0, *uh, *ul, *pwh;
    SYM(emb, g_emb); SYM(qkv, g_qkv); SYM(sc, g_sc); SYM(ct, g_ct); SYM(st, g_st);
    SYM(eh, g_eh); SYM(el, g_el); SYM(wqkvh, g_wqkvh);
    SYM(qh, g_qh); SYM(ql, g_ql); SYM(kh, g_kh); SYM(kl, g_kl);
    SYM(vth, g_vth); SYM(vtl, g_vtl); SYM(ph, g_ph); SYM(pl, g_pl);
    SYM(o2h, g_o2h); SYM(o2l, g_o2l); SYM(wph, g_wph); SYM(wpl, g_wpl);
    SYM(wuh, g_wuh); SYM(wgh, g_wgh); SYM(wdh, g_wdh);
    SYM(hh, g_hh); SYM(hl, g_hl);
    SYM(uh0, g_uh0); SYM(ul0, g_ul0); SYM(gh0, g_gh0); SYM(gl0, g_gl0);
    SYM(uh, g_uh); SYM(ul, g_ul); SYM(pwh, g_pwh);

    const int SMS128 = 2 * 2 * (128 * 176 + 128 * 176);   // MODE2 BN=128
    const int SMS64  = 2 * 2 * (128 * 176 + 64 * 176);    // MODE2 BN=64
    const int SM1128 = 2 * (2 * 128 * 176 + 128 * 176);   // MODE1 BN=128
    const int SMU128 = 2 * (128 * 176 + 128 * 176);       // MODE0 BN=128
    cudaFuncSetAttribute(tgemm_k<128,1,0,false,false,false,false>, cudaFuncAttributeMaxDynamicSharedMemorySize, SM1128);
    cudaFuncSetAttribute(tgemm_k<128,2,0,false,false,true ,false>, cudaFuncAttributeMaxDynamicSharedMemorySize, SMS128);
    cudaFuncSetAttribute(tgemm_k<128,2,0,true ,false,false,false>, cudaFuncAttributeMaxDynamicSharedMemorySize, SMS128);
    cudaFuncSetAttribute(tgemm_k<64 ,2,3,false,false,false,true >, cudaFuncAttributeMaxDynamicSharedMemorySize, SMS64);
    cudaFuncSetAttribute(tgemm_k<128,1,1,false,false,false,false>, cudaFuncAttributeMaxDynamicSharedMemorySize, SM1128);
    cudaFuncSetAttribute(tgemm_k<128,1,2,true ,false,false,false>, cudaFuncAttributeMaxDynamicSharedMemorySize, SM1128);
    cudaFuncSetAttribute(tgemm_k<128,0,0,false,true ,false,false>, cudaFuncAttributeMaxDynamicSharedMemorySize, SMU128);

    embed_k <<<kBS * kE / 256, 256>>>(tokens, table, emb, eh, el);
    costab_k<<<kS * kD / 256, 256>>>(ct, st);

    for (int l = 0; l < 4; l++) {
        const float* wq = Wq    + (size_t)l * kH * kE * kD;
        const float* wk = Wk    + (size_t)l * kH * kE * kD;
        const float* wv = Wv    + (size_t)l * kH * kE * kD;
        const float* wp = Wproj + (size_t)l * kE * kE;
        const float* nw = normw + (size_t)l * kE;
        const float* wu = Wup   + (size_t)l * kE * kF;
        const float* wg = Wgate + (size_t)l * kE * kF;
        const float* wd = Wdown + (size_t)l * kF * kE;

        // QKV ONE-SIDED (act split, weight fp16)
        wqkv_k<<<kQKV * kE / 256, 256>>>(wq, wk, wv, wqkvh);
        tgemm_k<128,1,0,false,false,false,false><<<dim3(kQKV/128, kBS/128), 256, SM1128>>>(
            eh, el, kE, 0, wqkvh, nullptr, kE, 0, qkv, nullptr, nullptr, kQKV, 0, nullptr, 1.f, kE);
        rope_k<<<kBS * kQKV / 256, 256>>>(qkv, ct, st, qh, ql, kh, kl, vth, vtl);

        // scores (full split, causal tile-skip)
        tgemm_k<128,2,0,false,false,true,false><<<dim3(kS/128, kS/128, kBH), 256, SMS128>>>(
            qh, ql, kD, (long long)kS*kD, kh, kl, kD, (long long)kS*kD,
            sc, nullptr, nullptr, kS, (long long)kS*kS, nullptr, 0.125f, kD);
        softmax_k<<<kBH * kS, 256>>>(sc, ph, pl);

        // o = P @ V (full split, causal K-bound) -> o2h/o2l directly
        tgemm_k<64,2,3,false,false,false,true><<<dim3(1, kS/128, kBH), 256, SMS64>>>(
            ph, pl, kS, (long long)kS*kS, vth, vtl, kS, (long long)kD*kS,
            nullptr, o2h, o2l, kD, (long long)kS*kD, nullptr, 1.f, kS);

        // emb += o2 @ Wproj (full split)
        wtr_k<<<dim3(kE/32, kE/32), dim3(32,8)>>>(wp, wph, wpl, kE, kE);
        tgemm_k<128,2,0,true,false,false,false><<<dim3(kE/128, kBS/128), 256, SMS128>>>(
            o2h, o2l, kE, 0, wph, wpl, kE, 0, emb, nullptr, nullptr, kE, 0, nullptr, 1.f, kE);

        // MLP: up/gate/down one-sided; up/gate emit hi/lo
        rmsnorm_k<<<kBS, 256>>>(emb, nw, hh, hl);
        wtr_k<<<dim3(kF/32, kE/32), dim3(32,8)>>>(wu, wuh, nullptr, kE, kF);
        wtr_k<<<dim3(kF/32, kE/32), dim3(32,8)>>>(wg, wgh, nullptr, kE, kF);
        tgemm_k<128,1,1,false,false,false,false><<<dim3(kF/128, kBS/128), 256, SM1128>>>(
            hh, hl, kE, 0, wuh, nullptr, kE, 0, nullptr, uh0, ul0, kF, 0, nullptr, 1.f, kE);
        tgemm_k<128,1,1,false,false,false,false><<<dim3(kF/128, kBS/128), 256, SM1128>>>(
            hh, hl, kE, 0, wgh, nullptr, kE, 0, nullptr, gh0, gl0, kF, 0, nullptr, 1.f, kE);
        elumul_k<<<kBS * kF / 256, 256>>>(uh0, ul0, gh0, gl0, uh, ul);
        wtr_k<<<dim3(kE/32, kF/32), dim3(32,8)>>>(wd, wdh, nullptr, kF, kE);
        tgemm_k<128,1,2,true,false,false,false><<<dim3(kE/128, kBS/128), 256, SM1128>>>(
            uh, ul, kF, 0, wdh, nullptr, kF, 0, emb, eh, el, kE, 0, nullptr, 1.f, kF);
    }

    // logits (unsplit fp16, fp32 acc) = emb @ predW + predB
    wtr_k<<<dim3(kV/32, kE/32), dim3(32,8)>>>(predW, pwh, nullptr, kE, kV);
    tgemm_k<128,0,0,false,true,false,false><<<dim3(kV/128, kBS/128), 256, SMU128>>>(
        eh, nullptr, kE, 0, pwh, nullptr, kE, 0, logits, nullptr, nullptr, kV, 0, predB, 1.f, kE);
}

// round 15
// speedup vs baseline: 1.0448x; 1.0448x over previous
#include <cuda_runtime.h>
#include <cuda_fp16.h>
#include <math.h>
#include <stdint.h>

namespace {
constexpr int kB = 2, kS = 1024, kE = 1024, kH = 16, kD = 64, kF = 4096, kV = 32000;
constexpr int kBS = kB * kS, kBH = kB * kH, kQKV = 3 * kE;
}

// ------------------------- device scratch -------------------------
__device__ float  g_emb [kBS * kE];
__device__ float  g_qkv [kBS * kQKV];
__device__ float  g_sc  [(size_t)kBH * kS * kS];
__device__ float  g_ct  [kS * kD];
__device__ float  g_st  [kS * kD];

__device__ __half g_eh[kBS*kE], g_el[kBS*kE];
__device__ __half g_qh[kBH*kS*kD], g_ql[kBH*kS*kD];
__device__ __half g_kh[kBH*kS*kD], g_kl[kBH*kS*kD];
__device__ __half g_vth[kBH*kD*kS], g_vtl[kBH*kD*kS];
__device__ __half g_ph[(size_t)kBH*kS*kS], g_pl[(size_t)kBH*kS*kS];
__device__ __half g_o2h[kBS*kE], g_o2l[kBS*kE];
__device__ __half g_hh[kBS*kE],  g_hl[kBS*kE];
__device__ __half g_uh0[kBS*kF], g_ul0[kBS*kF];
__device__ __half g_gh0[kBS*kF], g_gl0[kBS*kF];
__device__ __half g_uh[kBS*kF],  g_ul[kBS*kF];

// per-layer weight buffers (filled on side stream, consumed per layer)
__device__ __half g_wqkvh[4*(size_t)kQKV*kE];
__device__ __half g_wph[4*(size_t)kE*kE], g_wpl[4*(size_t)kE*kE];
__device__ __half g_wuh[4*(size_t)kF*kE];
__device__ __half g_wgh[4*(size_t)kF*kE];
__device__ __half g_wdh[4*(size_t)kE*kF];
__device__ __half g_pwh[(size_t)kV*kE];

// ------------------------- stream/event plumbing (created once) -------------
struct Aux {
    cudaStream_t s2;
    cudaEvent_t fork, w[5];
    Aux() {
        cudaStreamCreateWithFlags(&s2, cudaStreamNonBlocking);
        cudaEventCreateWithFlags(&fork, cudaEventDisableTiming);
        for (int i = 0; i < 5; i++) cudaEventCreateWithFlags(&w[i], cudaEventDisableTiming);
    }
};
static Aux g_aux;

// ------------------------- PTX helpers -------------------------
__device__ __forceinline__ uint32_t smem_u32(const void* p) {
    uint32_t a;
    asm("{ .reg .u64 t; cvta.to.shared.u64 t, %1; cvt.u32.u64 %0, t; }" : "=r"(a) : "l"(p));
    return a;
}
__device__ __forceinline__ void cpasync16(uint32_t dst, const void* src) {
    asm volatile("cp.async.cg.shared.global [%0], [%1], 16;" :: "r"(dst), "l"(src));
}
#define CP_COMMIT() asm volatile("cp.async.commit_group;" ::: "memory")
#define CP_WAIT0()  asm volatile("cp.async.wait_group 0;" ::: "memory")

__device__ __forceinline__ void ldsm4(uint32_t* r, uint32_t addr) {
    asm volatile("ldmatrix.sync.aligned.m8n8.x4.shared.b16 {%0,%1,%2,%3}, [%4];"
        : "=r"(r[0]), "=r"(r[1]), "=r"(r[2]), "=r"(r[3]) : "r"(addr));
}
__device__ __forceinline__ void hmma(float* c, const uint32_t* a, const uint32_t* b) {
    asm volatile("mma.sync.aligned.m16n8k16.row.col.f32.f16.f16.f32 "
        "{%0,%1,%2,%3}, {%4,%5,%6,%7}, {%8,%9}, {%0,%1,%2,%3};"
        : "+f"(c[0]), "+f"(c[1]), "+f"(c[2]), "+f"(c[3])
        : "r"(a[0]), "r"(a[1]), "r"(a[2]), "r"(a[3]), "r"(b[0]), "r"(b[1]));
}
__device__ __forceinline__ void hmma16(uint32_t* c, const uint32_t* a, const uint32_t* b) {
    asm volatile("mma.sync.aligned.m16n8k16.row.col.f16.f16.f16.f16 "
        "{%0,%1}, {%2,%3,%4,%5}, {%6,%7}, {%0,%1};"
        : "+r"(c[0]), "+r"(c[1])
        : "r"(a[0]), "r"(a[1]), "r"(a[2]), "r"(a[3]), "r"(b[0]), "r"(b[1]));
}
__device__ __forceinline__ void split2(float v, __half* h, __half* l) {
    __half hi = __float2half(v);
    *h = hi;
    *l = __float2half((v - __half2float(hi)) * 1024.f);
}

// stage one ROWS x 64 fp16 tile into 176B-padded smem rows (conflict-free ldsm)
template<int ROWS, int TPB>
__device__ __forceinline__ void stage_cp(uint32_t dst, const __half* __restrict__ src,
                                         long long ld, int k0, int tid)
{
#pragma unroll
    for (int it = 0; it < ROWS * 8 / TPB; it++) {
        int i = it * TPB + tid;
        int r = i >> 3, c = i & 7;
        cpasync16(dst + r * 176 + c * 16, src + (long long)r * ld + k0 + c * 8);
    }
}

// ------------------------- HMMA GEMM (R13 shape: 512 thr, 4x4 warps) --------
// MODE 2: full hi/lo split. MODE 1: A split, B hi. MODE 0: plain fp16.
// OUT 0: fp32 C.  OUT 1: hi/lo -> Ch/Cl.  OUT 2: fp32 C (+ACCUM) AND Ch/Cl.
// OUT 3: hi/lo at attention map [(b,h),s,d] -> ((b*kS+s)<<10)+(h<<6)+d.
// CAUSAL: skip tiles above diagonal. CAUSK: clamp K at (by+1)*128.
template<int BN, int MODE, int OUT, bool ACCUM, bool BIAS, bool CAUSAL, bool CAUSK>
__global__ void __launch_bounds__(512, 1)
tgemm_k(const __half* __restrict__ Ah, const __half* __restrict__ Al, int lda, long long sA,
        const __half* __restrict__ Bh, const __half* __restrict__ Bl, int ldb, long long sB,
        float* __restrict__ C, __half* __restrict__ Ch, __half* __restrict__ Cl,
        int ldc, long long sC,
        const float* __restrict__ bias, float alpha, int K)
{
    constexpr int BM = 128, BK = 64, TPB = 512;
    constexpr int WM = 4, WN = 4;
    constexpr int MT = BM / (WM * 16);
    constexpr int NT = BN / (WN * 8);
    constexpr int TILEA = BM * 176;
    constexpr int TILEB = BN * 176;
    constexpr int NA = (MODE >= 1) ? 2 : 1;
    constexpr int NB = (MODE == 2) ? 2 : 1;
    constexpr int STAGE = NA * TILEA + NB * TILEB;

    const int bx = blockIdx.x, by = blockIdx.y, bz = blockIdx.z;
    if (CAUSAL && bx * BN > by * BM + BM - 1) return;
    int Ktot = K;
    if (CAUSK) { int km = (by + 1) * BM; if (km < Ktot) Ktot = km; }
    const int NC = Ktot / BK;

    extern __shared__ char sm[];
    const uint32_t sb = smem_u32(sm);
    const int tid = threadIdx.x, lane = tid & 31, wid = tid >> 5;
    const int m0 = (wid / WN) * MT * 16;
    const int n0 = (wid % WN) * NT * 8;

    const __half* pAh = Ah + bz * sA + (long long)by * BM * lda;
    const __half* pAl = (MODE >= 1) ? Al + bz * sA + (long long)by * BM * lda : nullptr;
    const __half* pBh = Bh + bz * sB + (long long)bx * BN * ldb;
    const __half* pBl = (MODE == 2) ? Bl + bz * sB + (long long)bx * BN * ldb : nullptr;

    float    acc1[MT][NT][4];
    uint32_t acc2[MT][NT][2];
#pragma unroll
    for (int mt = 0; mt < MT; mt++)
#pragma unroll
        for (int nt = 0; nt < NT; nt++) {
#pragma unroll
            for (int i = 0; i < 4; i++) acc1[mt][nt][i] = 0.f;
            acc2[mt][nt][0] = 0u; acc2[mt][nt][1] = 0u;
        }

    auto stage_all = [&](int buf, int k0) {
        uint32_t s0 = sb + (uint32_t)buf * STAGE;
        stage_cp<BM, TPB>(s0, pAh, lda, k0, tid);
        stage_cp<BN, TPB>(s0 + NA*TILEA, pBh, ldb, k0, tid);
        if (MODE >= 1) stage_cp<BM, TPB>(s0 + TILEA, pAl, lda, k0, tid);
        if (MODE == 2) stage_cp<BN, TPB>(s0 + NA*TILEA + TILEB, pBl, ldb, k0, tid);
    };

    stage_all(0, 0); CP_COMMIT();

    for (int i = 0; i < NC; i++) {
        CP_WAIT0();
        __syncthreads();
        if (i + 1 < NC) { stage_all((i + 1) & 1, (i + 1) * BK); CP_COMMIT(); }

        const uint32_t s0 = sb + (uint32_t)(i & 1) * STAGE;
        const uint32_t aH = s0, aL = s0 + TILEA;
        const uint32_t bH = s0 + NA*TILEA, bL = s0 + NA*TILEA + TILEB;

#pragma unroll
        for (int ks = 0; ks < 4; ks++) {
            const int kc = ks * 2;
            uint32_t ah[MT][4], al[MT][4], bhf[NT][2], blf[NT][2];

#pragma unroll
            for (int nt = 0; nt < NT; nt += 2) {
                const int g = lane >> 3;
                const uint32_t off =
                    (uint32_t)(n0 + nt * 8 + ((g >> 1) << 3) + (lane & 7)) * 176
                    + (uint32_t)(kc + (g & 1)) * 16;
                uint32_t r[4];
                ldsm4(r, bH + off);
                bhf[nt][0] = r[0]; bhf[nt][1] = r[1];
                bhf[nt+1][0] = r[2]; bhf[nt+1][1] = r[3];
                if (MODE == 2) {
                    ldsm4(r, bL + off);
                    blf[nt][0] = r[0]; blf[nt][1] = r[1];
                    blf[nt+1][0] = r[2]; blf[nt+1][1] = r[3];
                }
            }
#pragma unroll
            for (int mt = 0; mt < MT; mt++) {
                const uint32_t off =
                    (uint32_t)(m0 + mt * 16 + (lane & 15)) * 176
                    + (uint32_t)(kc + (lane >> 4)) * 16;
                ldsm4(ah[mt], aH + off);
                if (MODE >= 1) ldsm4(al[mt], aL + off);
            }
#pragma unroll
            for (int mt = 0; mt < MT; mt++)
#pragma unroll
                for (int nt = 0; nt < NT; nt++) {
                    hmma(acc1[mt][nt], ah[mt], bhf[nt]);
                    if (MODE == 2) hmma16(acc2[mt][nt], ah[mt], blf[nt]);
                    if (MODE >= 1) hmma16(acc2[mt][nt], al[mt], bhf[nt]);
                }
        }
    }

    // ---- epilogue ----
    const float inv = 1.f / 1024.f;
#pragma unroll
    for (int mt = 0; mt < MT; mt++) {
#pragma unroll
        for (int nt = 0; nt < NT; nt++) {
            const int row = by * BM + m0 + mt * 16 + (lane >> 2);
            const int col = bx * BN + n0 + nt * 8 + ((lane & 3) << 1);
#pragma unroll
            for (int h = 0; h < 2; h++) {
                const int r = row + h * 8;
                float v0 = acc1[mt][nt][2*h], v1 = acc1[mt][nt][2*h+1];
                if (MODE >= 1) {
                    __half2 c2 = *reinterpret_cast<__half2*>(&acc2[mt][nt][h]);
                    v0 += __low2float(c2) * inv;
                    v1 += __high2float(c2) * inv;
                }
                v0 *= alpha; v1 *= alpha;
                if (BIAS) { v0 += bias[col]; v1 += bias[col + 1]; }

                if (OUT == 0 || OUT == 2) {
                    float* Cp = C + bz * sC + (long long)r * ldc + col;
                    float a0 = v0, a1 = v1;
                    if (ACCUM) { float2 o = *reinterpret_cast<float2*>(Cp); a0 += o.x; a1 += o.y; }
                    *reinterpret_cast<float2*>(Cp) = make_float2(a0, a1);
                    if (OUT == 2) { v0 = a0; v1 = a1; }
                }
                if (OUT >= 1) {
                    size_t idx;
                    if (OUT == 3) {
                        int bb = bz >> 4, hh = bz & 15;
                        idx = (((size_t)(bb * kS + r)) << 10) + (hh << 6) + col;
                    } else {
                        idx = (size_t)bz * sC + (size_t)r * ldc + col;
                    }
                    __half h0, l0, h1, l1;
                    split2(v0, &h0, &l0);
                    split2(v1, &h1, &l1);
                    *reinterpret_cast<__half2*>(Ch + idx) = __halves2half2(h0, h1);
                    *reinterpret_cast<__half2*>(Cl + idx) = __halves2half2(l0, l1);
                }
            }
        }
    }
}

// ------------------------- elementwise kernels -------------------------
__global__ void embed_k(const int* __restrict__ tok, const float* __restrict__ tab,
                        float* __restrict__ out, __half* __restrict__ eh, __half* __restrict__ el)
{
    int idx = blockIdx.x * blockDim.x + threadIdx.x;
    float v = tab[(size_t)tok[idx >> 10] * kE + (idx & 1023)];
    out[idx] = v; split2(v, eh + idx, el + idx);
}

__global__ void costab_k(float* __restrict__ ct, float* __restrict__ st)
{
    int idx = blockIdx.x * blockDim.x + threadIdx.x;
    int s = idx / kD, i = idx % kD;
    float theta = powf(10000.f, (-2.f / kD) * (float)(i & 31));
    ct[idx] = cosf((float)s * theta);
    st[idx] = sinf((float)s * theta) * (i < kD/2 ? -1.f : 1.f);
}

__global__ void wqkv_k(const float* __restrict__ wq, const float* __restrict__ wk,
                       const float* __restrict__ wv, __half* __restrict__ h)
{
    int idx = blockIdx.x * blockDim.x + threadIdx.x;
    int n = idx / kE, e = idx % kE;
    int seg = n >> 10, hh = (n & 1023) >> 6, k = n & 63;
    const float* w = seg == 0 ? wq : seg == 1 ? wk : wv;
    h[idx] = __float2half(w[((size_t)hh * kE + e) * kD + k]);
}

__global__ void wtr_k(const float* __restrict__ src, __half* __restrict__ dh,
                      __half* __restrict__ dl, int K, int N)
{
    __shared__ float t[32][33];
    int k0 = blockIdx.y * 32, n0 = blockIdx.x * 32;
    for (int r = threadIdx.y; r < 32; r += 8)
        t[r][threadIdx.x] = src[(size_t)(k0 + r) * N + n0 + threadIdx.x];
    __syncthreads();
    for (int r = threadIdx.y; r < 32; r += 8) {
        size_t o = (size_t)(n0 + r) * K + k0 + threadIdx.x;
        float v = t[threadIdx.x][r];
        if (dl) split2(v, dh + o, dl + o);
        else    dh[o] = __float2half(v);
    }
}

__global__ void rope_k(const float* __restrict__ qkv, const float* __restrict__ ct,
                       const float* __restrict__ st,
                       __half* __restrict__ qh, __half* __restrict__ ql,
                       __half* __restrict__ kh, __half* __restrict__ kl,
                       __half* __restrict__ vth, __half* __restrict__ vtl)
{
    int idx = blockIdx.x * blockDim.x + threadIdx.x;
    int row = idx / kQKV, c = idx % kQKV;
    int b = row >> 10, s = row & 1023;
    int seg = c >> 10, h = (c & 1023) >> 6, i = c & 63;
    float x = qkv[idx];
    if (seg == 2) {
        size_t dst = ((size_t)(b * kH + h) * kD + i) * kS + s;
        split2(x, vth + dst, vtl + dst);
        return;
    }
    float sw = qkv[(size_t)row * kQKV + (seg << 10) + (h << 6) + ((i + 32) & 63)];
    float val = ct[(s << 6) + i] * x + st[(s << 6) + i] * sw;
    size_t dst = ((size_t)(b * kH + h) * kS + s) * kD + i;
    if (seg == 0) split2(val, qh + dst, ql + dst);
    else          split2(val, kh + dst, kl + dst);
}

__global__ void softmax_k(const float* __restrict__ sc,
                          __half* __restrict__ ph, __half* __restrict__ pl)
{
    const int r = blockIdx.x, s = r & (kS - 1), n = s + 1, t = threadIdx.x;
    const int kend = ((s >> 7) + 1) << 7;
    const float* row = sc + (size_t)r * kS;
    __half* prh = ph + (size_t)r * kS;
    __half* prl = pl + (size_t)r * kS;
    __shared__ float red[256];

    float v[4];
#pragma unroll
    for (int j = 0; j < 4; j++) {
        int i = t + j * 256;
        v[j] = (i < n) ? row[i] : -INFINITY;
    }
    float m = fmaxf(fmaxf(v[0], v[1]), fmaxf(v[2], v[3]));
    red[t] = m; __syncthreads();
    for (int o = 128; o > 0; o >>= 1) { if (t < o) red[t] = fmaxf(red[t], red[t+o]); __syncthreads(); }
    m = red[0]; __syncthreads();

    float e[4], sum = 0.f;
#pragma unroll
    for (int j = 0; j < 4; j++) {
        int i = t + j * 256;
        e[j] = (i < n) ? expf(v[j] - m) : 0.f;
        sum += e[j];
    }
    red[t] = sum; __syncthreads();
    for (int o = 128; o > 0; o >>= 1) { if (t < o) red[t] += red[t+o]; __syncthreads(); }
    float inv = 1.f / red[0];
#pragma unroll
    for (int j = 0; j < 4; j++) {
        int i = t + j * 256;
        if (i < kend) split2(e[j] * inv, prh + i, prl + i);
    }
}

__global__ void rmsnorm_k(const float* __restrict__ x, const float* __restrict__ w,
                          __half* __restrict__ yh, __half* __restrict__ yl)
{
    const int r = blockIdx.x, t = threadIdx.x;
    const float* xr = x + (size_t)r * kE;
    __shared__ float red[256];
    float sum = 0.f;
    for (int i = t; i < kE; i += 256) { float v = xr[i]; sum += v * v; }
    red[t] = sum; __syncthreads();
    for (int o = 128; o > 0; o >>= 1) { if (t < o) red[t] += red[t+o]; __syncthreads(); }
    float rs = rsqrtf(red[0] / kE + 1.1920929e-7f);
    for (int i = t; i < kE; i += 256) {
        size_t o = (size_t)r * kE + i;
        split2(xr[i] * rs * w[i], yh + o, yl + o);
    }
}

__global__ void elumul_k(const __half* __restrict__ uh0, const __half* __restrict__ ul0,
                         const __half* __restrict__ gh0, const __half* __restrict__ gl0,
                         __half* __restrict__ uh, __half* __restrict__ ul)
{
    int i = blockIdx.x * blockDim.x + threadIdx.x;
    float u = __half2float(uh0[i]) + __half2float(ul0[i]) * (1.f/1024.f);
    float g = __half2float(gh0[i]) + __half2float(gl0[i]) * (1.f/1024.f);
    float e = g > 0.f ? g : expm1f(g);
    split2(u * e, uh + i, ul + i);
}

// ------------------------- host launcher -------------------------
#define SYM(p, s) cudaGetSymbolAddress((void**)&p, s)

extern "C" void kernel_launch(void* const* d_in, const int* in_sizes, int n_in,
                              void* d_out, int out_size)
{
    (void)in_sizes; (void)n_in; (void)out_size;
    const int*   tokens = (const int*)  d_in[0];
    const float* table = (const float*)d_in[1];
    const float *Wq = (const float*)d_in[2], *Wk = (const float*)d_in[3], *Wv = (const float*)d_in[4];
    const float *Wproj = (const float*)d_in[5], *normw = (const float*)d_in[6];
    const float *Wup = (const float*)d_in[7], *Wgate = (const float*)d_in[8], *Wdown = (const float*)d_in[9];
    const float *predW = (const float*)d_in[10], *predB = (const float*)d_in[11];
    float* logits = (float*)d_out;

    float *emb, *qkv, *sc, *ct, *st;
    __half *eh, *el, *qh, *ql, *kh, *kl, *vth, *vtl, *ph, *pl;
    __half *o2h, *o2l, *hh, *hl, *uh0, *ul0, *gh0, *gl0, *uh, *ul;
    __half *wqkvh, *wph, *wpl, *wuh, *wgh, *wdh, *pwh;
    SYM(emb, g_emb); SYM(qkv, g_qkv); SYM(sc, g_sc); SYM(ct, g_ct); SYM(st, g_st);
    SYM(eh, g_eh); SYM(el, g_el);
    SYM(qh, g_qh); SYM(ql, g_ql); SYM(kh, g_kh); SYM(kl, g_kl);
    SYM(vth, g_vth); SYM(vtl, g_vtl); SYM(ph, g_ph); SYM(pl, g_pl);
    SYM(o2h, g_o2h); SYM(o2l, g_o2l); SYM(hh, g_hh); SYM(hl, g_hl);
    SYM(uh0, g_uh0); SYM(ul0, g_ul0); SYM(gh0, g_gh0); SYM(gl0, g_gl0);
    SYM(uh, g_uh); SYM(ul, g_ul);
    SYM(wqkvh, g_wqkvh); SYM(wph, g_wph); SYM(wpl, g_wpl);
    SYM(wuh, g_wuh); SYM(wgh, g_wgh); SYM(wdh, g_wdh); SYM(pwh, g_pwh);

    const int SMS128 = 2 * 2 * (128 * 176 + 128 * 176);
    const int SMS64  = 2 * 2 * (128 * 176 + 64 * 176);
    const int SM1128 = 2 * (2 * 128 * 176 + 128 * 176);
    const int SMU128 = 2 * (128 * 176 + 128 * 176);
    cudaFuncSetAttribute(tgemm_k<128,1,0,false,false,false,false>, cudaFuncAttributeMaxDynamicSharedMemorySize, SM1128);
    cudaFuncSetAttribute(tgemm_k<128,2,0,false,false,true ,false>, cudaFuncAttributeMaxDynamicSharedMemorySize, SMS128);
    cudaFuncSetAttribute(tgemm_k<128,2,0,true ,false,false,false>, cudaFuncAttributeMaxDynamicSharedMemorySize, SMS128);
    cudaFuncSetAttribute(tgemm_k<64 ,2,3,false,false,false,true >, cudaFuncAttributeMaxDynamicSharedMemorySize, SMS64);
    cudaFuncSetAttribute(tgemm_k<128,1,1,false,false,false,false>, cudaFuncAttributeMaxDynamicSharedMemorySize, SM1128);
    cudaFuncSetAttribute(tgemm_k<128,1,2,true ,false,false,false>, cudaFuncAttributeMaxDynamicSharedMemorySize, SM1128);
    cudaFuncSetAttribute(tgemm_k<128,0,0,false,true ,false,false>, cudaFuncAttributeMaxDynamicSharedMemorySize, SMU128);

    cudaStream_t s2 = g_aux.s2;

    // fork side stream from the captured default stream
    cudaEventRecord(g_aux.fork, 0);
    cudaStreamWaitEvent(s2, g_aux.fork, 0);

    // ---- weight prep for all layers + logits on s2 ----
    for (int l = 0; l < 4; l++) {
        const float* wq = Wq    + (size_t)l * kH * kE * kD;
        const float* wk = Wk    + (size_t)l * kH * kE * kD;
        const float* wv = Wv    + (size_t)l * kH * kE * kD;
        const float* wp = Wproj + (size_t)l * kE * kE;
        const float* wu = Wup   + (size_t)l * kE * kF;
        const float* wg = Wgate + (size_t)l * kE * kF;
        const float* wd = Wdown + (size_t)l * kF * kE;
        wqkv_k<<<kQKV * kE / 256, 256, 0, s2>>>(wq, wk, wv, wqkvh + (size_t)l*kQKV*kE);
        wtr_k<<<dim3(kE/32, kE/32), dim3(32,8), 0, s2>>>(wp, wph + (size_t)l*kE*kE, wpl + (size_t)l*kE*kE, kE, kE);
        wtr_k<<<dim3(kF/32, kE/32), dim3(32,8), 0, s2>>>(wu, wuh + (size_t)l*kF*kE, nullptr, kE, kF);
        wtr_k<<<dim3(kF/32, kE/32), dim3(32,8), 0, s2>>>(wg, wgh + (size_t)l*kF*kE, nullptr, kE, kF);
        wtr_k<<<dim3(kE/32, kF/32), dim3(32,8), 0, s2>>>(wd, wdh + (size_t)l*kE*kF, nullptr, kF, kE);
        cudaEventRecord(g_aux.w[l], s2);
    }
    wtr_k<<<dim3(kV/32, kE/32), dim3(32,8), 0, s2>>>(predW, pwh, nullptr, kE, kV);
    cudaEventRecord(g_aux.w[4], s2);

    // ---- main compute on default stream ----
    embed_k <<<kBS * kE / 256, 256>>>(tokens, table, emb, eh, el);
    costab_k<<<kS * kD / 256, 256>>>(ct, st);

    for (int l = 0; l < 4; l++) {
        const float* nw = normw + (size_t)l * kE;
        __half* lwqkv = wqkvh + (size_t)l*kQKV*kE;
        __half* lwph  = wph  + (size_t)l*kE*kE;
        __half* lwpl  = wpl  + (size_t)l*kE*kE;
        __half* lwuh  = wuh  + (size_t)l*kF*kE;
        __half* lwgh  = wgh  + (size_t)l*kF*kE;
        __half* lwdh  = wdh  + (size_t)l*kE*kF;

        cudaStreamWaitEvent(0, g_aux.w[l], 0);

        // QKV one-sided
        tgemm_k<128,1,0,false,false,false,false><<<dim3(kQKV/128, kBS/128), 512, SM1128>>>(
            eh, el, kE, 0, lwqkv, nullptr, kE, 0, qkv, nullptr, nullptr, kQKV, 0, nullptr, 1.f, kE);
        rope_k<<<kBS * kQKV / 256, 256>>>(qkv, ct, st, qh, ql, kh, kl, vth, vtl);

        // scores (full split, causal tile-skip)
        tgemm_k<128,2,0,false,false,true,false><<<dim3(kS/128, kS/128, kBH), 512, SMS128>>>(
            qh, ql, kD, (long long)kS*kD, kh, kl, kD, (long long)kS*kD,
            sc, nullptr, nullptr, kS, (long long)kS*kS, nullptr, 0.125f, kD);
        softmax_k<<<kBH * kS, 256>>>(sc, ph, pl);

        // o = P @ V (full split, causal K-bound) -> o2h/o2l directly
        tgemm_k<64,2,3,false,false,false,true><<<dim3(1, kS/128, kBH), 512, SMS64>>>(
            ph, pl, kS, (long long)kS*kS, vth, vtl, kS, (long long)kD*kS,
            nullptr, o2h, o2l, kD, (long long)kS*kD, nullptr, 1.f, kS);

        // emb += o2 @ Wproj (full split)
        tgemm_k<128,2,0,true,false,false,false><<<dim3(kE/128, kBS/128), 512, SMS128>>>(
            o2h, o2l, kE, 0, lwph, lwpl, kE, 0, emb, nullptr, nullptr, kE, 0, nullptr, 1.f, kE);

        // MLP: up/gate/down one-sided; up/gate emit hi/lo
        rmsnorm_k<<<kBS, 256>>>(emb, nw, hh, hl);
        tgemm_k<128,1,1,false,false,false,false><<<dim3(kF/128, kBS/128), 512, SM1128>>>(
            hh, hl, kE, 0, lwuh, nullptr, kE, 0, nullptr, uh0, ul0, kF, 0, nullptr, 1.f, kE);
        tgemm_k<128,1,1,false,false,false,false><<<dim3(kF/128, kBS/128), 512, SM1128>>>(
            hh, hl, kE, 0, lwgh, nullptr, kE, 0, nullptr, gh0, gl0, kF, 0, nullptr, 1.f, kE);
        elumul_k<<<kBS * kF / 256, 256>>>(uh0, ul0, gh0, gl0, uh, ul);
        tgemm_k<128,1,2,true,false,false,false><<<dim3(kE/128, kBS/128), 512, SM1128>>>(
            uh, ul, kF, 0, lwdh, nullptr, kF, 0, emb, eh, el, kE, 0, nullptr, 1.f, kF);
    }

    // join side stream fully, then logits (unsplit fp16)
    cudaStreamWaitEvent(0, g_aux.w[4], 0);
    tgemm_k<128,0,0,false,true,false,false><<<dim3(kV/128, kBS/128), 512, SMU128>>>(
        eh, nullptr, kE, 0, pwh, nullptr, kE, 0, logits, nullptr, nullptr, kV, 0, predB, 1.f, kE);
}

// round 16
// speedup vs baseline: 1.0805x; 1.0342x over previous
#include <cuda_runtime.h>
#include <cuda_fp16.h>
#include <math.h>
#include <stdint.h>

namespace {
constexpr int kB = 2, kS = 1024, kE = 1024, kH = 16, kD = 64, kF = 4096, kV = 32000;
constexpr int kBS = kB * kS, kBH = kB * kH, kQKV = 3 * kE, kF2 = 2 * kF;
}

// ------------------------- device scratch -------------------------
__device__ float  g_emb [kBS * kE];
__device__ float  g_qkv [kBS * kQKV];
__device__ float  g_sc  [(size_t)kBH * kS * kS];
__device__ float  g_ct  [kS * kD];
__device__ float  g_st  [kS * kD];

__device__ __half g_eh[kBS*kE], g_el[kBS*kE];
__device__ __half g_qh[kBH*kS*kD], g_ql[kBH*kS*kD];
__device__ __half g_kh[kBH*kS*kD], g_kl[kBH*kS*kD];
__device__ __half g_vth[kBH*kD*kS], g_vtl[kBH*kD*kS];
__device__ __half g_ph[(size_t)kBH*kS*kS], g_pl[(size_t)kBH*kS*kS];
__device__ __half g_o2h[kBS*kE], g_o2l[kBS*kE];
__device__ __half g_hh[kBS*kE],  g_hl[kBS*kE];
__device__ __half g_ug0h[(size_t)kBS*kF2], g_ug0l[(size_t)kBS*kF2];
__device__ __half g_uh[kBS*kF],  g_ul[kBS*kF];

// per-layer weight buffers (filled on side stream)
__device__ __half g_wqkvh[4*(size_t)kQKV*kE];
__device__ __half g_wph[4*(size_t)kE*kE], g_wpl[4*(size_t)kE*kE];
__device__ __half g_wugh[4*(size_t)kF2*kE];
__device__ __half g_wdh[4*(size_t)kE*kF];
__device__ __half g_pwh[(size_t)kV*kE];

// ------------------------- stream/event plumbing (created once) -------------
struct Aux {
    cudaStream_t s2;
    cudaEvent_t fork, eq[4], er[4], wlog;
    Aux() {
        cudaStreamCreateWithFlags(&s2, cudaStreamNonBlocking);
        cudaEventCreateWithFlags(&fork, cudaEventDisableTiming);
        for (int i = 0; i < 4; i++) {
            cudaEventCreateWithFlags(&eq[i], cudaEventDisableTiming);
            cudaEventCreateWithFlags(&er[i], cudaEventDisableTiming);
        }
        cudaEventCreateWithFlags(&wlog, cudaEventDisableTiming);
    }
};
static Aux g_aux;

// ------------------------- PTX helpers -------------------------
__device__ __forceinline__ uint32_t smem_u32(const void* p) {
    uint32_t a;
    asm("{ .reg .u64 t; cvta.to.shared.u64 t, %1; cvt.u32.u64 %0, t; }" : "=r"(a) : "l"(p));
    return a;
}
__device__ __forceinline__ void cpasync16(uint32_t dst, const void* src) {
    asm volatile("cp.async.cg.shared.global [%0], [%1], 16;" :: "r"(dst), "l"(src));
}
#define CP_COMMIT() asm volatile("cp.async.commit_group;" ::: "memory")
#define CP_WAIT0()  asm volatile("cp.async.wait_group 0;" ::: "memory")

__device__ __forceinline__ void ldsm4(uint32_t* r, uint32_t addr) {
    asm volatile("ldmatrix.sync.aligned.m8n8.x4.shared.b16 {%0,%1,%2,%3}, [%4];"
        : "=r"(r[0]), "=r"(r[1]), "=r"(r[2]), "=r"(r[3]) : "r"(addr));
}
__device__ __forceinline__ void hmma(float* c, const uint32_t* a, const uint32_t* b) {
    asm volatile("mma.sync.aligned.m16n8k16.row.col.f32.f16.f16.f32 "
        "{%0,%1,%2,%3}, {%4,%5,%6,%7}, {%8,%9}, {%0,%1,%2,%3};"
        : "+f"(c[0]), "+f"(c[1]), "+f"(c[2]), "+f"(c[3])
        : "r"(a[0]), "r"(a[1]), "r"(a[2]), "r"(a[3]), "r"(b[0]), "r"(b[1]));
}
__device__ __forceinline__ void hmma16(uint32_t* c, const uint32_t* a, const uint32_t* b) {
    asm volatile("mma.sync.aligned.m16n8k16.row.col.f16.f16.f16.f16 "
        "{%0,%1}, {%2,%3,%4,%5}, {%6,%7}, {%0,%1};"
        : "+r"(c[0]), "+r"(c[1])
        : "r"(a[0]), "r"(a[1]), "r"(a[2]), "r"(a[3]), "r"(b[0]), "r"(b[1]));
}
__device__ __forceinline__ void split2(float v, __half* h, __half* l) {
    __half hi = __float2half(v);
    *h = hi;
    *l = __float2half((v - __half2float(hi)) * 1024.f);
}

// stage one ROWS x 64 fp16 tile into 176B-padded smem rows (conflict-free ldsm)
template<int ROWS, int TPB>
__device__ __forceinline__ void stage_cp(uint32_t dst, const __half* __restrict__ src,
                                         long long ld, int k0, int tid)
{
#pragma unroll
    for (int it = 0; it < ROWS * 8 / TPB; it++) {
        int i = it * TPB + tid;
        int r = i >> 3, c = i & 7;
        cpasync16(dst + r * 176 + c * 16, src + (long long)r * ld + k0 + c * 8);
    }
}

// ------------------------- HMMA GEMM (512 thr, 4x4 warps) -------------------
// MODE 2: full hi/lo split. MODE 1: A split, B hi. MODE 0: plain fp16.
// OUT 0: fp32 C.  OUT 1: hi/lo -> Ch/Cl.  OUT 2: fp32 C (+ACCUM) AND Ch/Cl.
// OUT 3: hi/lo at attention map [(b,h),s,d] -> ((b*kS+s)<<10)+(h<<6)+d.
// CAUSAL: skip tiles above diagonal. CAUSK: clamp K at (by+1)*128.
template<int BN, int MODE, int OUT, bool ACCUM, bool BIAS, bool CAUSAL, bool CAUSK>
__global__ void __launch_bounds__(512, 1)
tgemm_k(const __half* __restrict__ Ah, const __half* __restrict__ Al, int lda, long long sA,
        const __half* __restrict__ Bh, const __half* __restrict__ Bl, int ldb, long long sB,
        float* __restrict__ C, __half* __restrict__ Ch, __half* __restrict__ Cl,
        int ldc, long long sC,
        const float* __restrict__ bias, float alpha, int K)
{
    constexpr int BM = 128, BK = 64, TPB = 512;
    constexpr int WM = 4, WN = 4;
    constexpr int MT = BM / (WM * 16);
    constexpr int NT = BN / (WN * 8);
    constexpr int TILEA = BM * 176;
    constexpr int TILEB = BN * 176;
    constexpr int NA = (MODE >= 1) ? 2 : 1;
    constexpr int NB = (MODE == 2) ? 2 : 1;
    constexpr int STAGE = NA * TILEA + NB * TILEB;

    const int bx = blockIdx.x, by = blockIdx.y, bz = blockIdx.z;
    if (CAUSAL && bx * BN > by * BM + BM - 1) return;
    int Ktot = K;
    if (CAUSK) { int km = (by + 1) * BM; if (km < Ktot) Ktot = km; }
    const int NC = Ktot / BK;

    extern __shared__ char sm[];
    const uint32_t sb = smem_u32(sm);
    const int tid = threadIdx.x, lane = tid & 31, wid = tid >> 5;
    const int m0 = (wid / WN) * MT * 16;
    const int n0 = (wid % WN) * NT * 8;

    const __half* pAh = Ah + bz * sA + (long long)by * BM * lda;
    const __half* pAl = (MODE >= 1) ? Al + bz * sA + (long long)by * BM * lda : nullptr;
    const __half* pBh = Bh + bz * sB + (long long)bx * BN * ldb;
    const __half* pBl = (MODE == 2) ? Bl + bz * sB + (long long)bx * BN * ldb : nullptr;

    float    acc1[MT][NT][4];
    uint32_t acc2[MT][NT][2];
#pragma unroll
    for (int mt = 0; mt < MT; mt++)
#pragma unroll
        for (int nt = 0; nt < NT; nt++) {
#pragma unroll
            for (int i = 0; i < 4; i++) acc1[mt][nt][i] = 0.f;
            acc2[mt][nt][0] = 0u; acc2[mt][nt][1] = 0u;
        }

    auto stage_all = [&](int buf, int k0) {
        uint32_t s0 = sb + (uint32_t)buf * STAGE;
        stage_cp<BM, TPB>(s0, pAh, lda, k0, tid);
        stage_cp<BN, TPB>(s0 + NA*TILEA, pBh, ldb, k0, tid);
        if (MODE >= 1) stage_cp<BM, TPB>(s0 + TILEA, pAl, lda, k0, tid);
        if (MODE == 2) stage_cp<BN, TPB>(s0 + NA*TILEA + TILEB, pBl, ldb, k0, tid);
    };

    stage_all(0, 0); CP_COMMIT();

    for (int i = 0; i < NC; i++) {
        CP_WAIT0();
        __syncthreads();
        if (i + 1 < NC) { stage_all((i + 1) & 1, (i + 1) * BK); CP_COMMIT(); }

        const uint32_t s0 = sb + (uint32_t)(i & 1) * STAGE;
        const uint32_t aH = s0, aL = s0 + TILEA;
        const uint32_t bH = s0 + NA*TILEA, bL = s0 + NA*TILEA + TILEB;

#pragma unroll
        for (int ks = 0; ks < 4; ks++) {
            const int kc = ks * 2;
            uint32_t ah[MT][4], al[MT][4], bhf[NT][2], blf[NT][2];

#pragma unroll
            for (int nt = 0; nt < NT; nt += 2) {
                const int g = lane >> 3;
                const uint32_t off =
                    (uint32_t)(n0 + nt * 8 + ((g >> 1) << 3) + (lane & 7)) * 176
                    + (uint32_t)(kc + (g & 1)) * 16;
                uint32_t r[4];
                ldsm4(r, bH + off);
                bhf[nt][0] = r[0]; bhf[nt][1] = r[1];
                bhf[nt+1][0] = r[2]; bhf[nt+1][1] = r[3];
                if (MODE == 2) {
                    ldsm4(r, bL + off);
                    blf[nt][0] = r[0]; blf[nt][1] = r[1];
                    blf[nt+1][0] = r[2]; blf[nt+1][1] = r[3];
                }
            }
#pragma unroll
            for (int mt = 0; mt < MT; mt++) {
                const uint32_t off =
                    (uint32_t)(m0 + mt * 16 + (lane & 15)) * 176
                    + (uint32_t)(kc + (lane >> 4)) * 16;
                ldsm4(ah[mt], aH + off);
                if (MODE >= 1) ldsm4(al[mt], aL + off);
            }
#pragma unroll
            for (int mt = 0; mt < MT; mt++)
#pragma unroll
                for (int nt = 0; nt < NT; nt++) {
                    hmma(acc1[mt][nt], ah[mt], bhf[nt]);
                    if (MODE == 2) hmma16(acc2[mt][nt], ah[mt], blf[nt]);
                    if (MODE >= 1) hmma16(acc2[mt][nt], al[mt], bhf[nt]);
                }
        }
    }

    // ---- epilogue ----
    const float inv = 1.f / 1024.f;
#pragma unroll
    for (int mt = 0; mt < MT; mt++) {
#pragma unroll
        for (int nt = 0; nt < NT; nt++) {
            const int row = by * BM + m0 + mt * 16 + (lane >> 2);
            const int col = bx * BN + n0 + nt * 8 + ((lane & 3) << 1);
#pragma unroll
            for (int h = 0; h < 2; h++) {
                const int r = row + h * 8;
                float v0 = acc1[mt][nt][2*h], v1 = acc1[mt][nt][2*h+1];
                if (MODE >= 1) {
                    __half2 c2 = *reinterpret_cast<__half2*>(&acc2[mt][nt][h]);
                    v0 += __low2float(c2) * inv;
                    v1 += __high2float(c2) * inv;
                }
                v0 *= alpha; v1 *= alpha;
                if (BIAS) { v0 += bias[col]; v1 += bias[col + 1]; }

                if (OUT == 0 || OUT == 2) {
                    float* Cp = C + bz * sC + (long long)r * ldc + col;
                    float a0 = v0, a1 = v1;
                    if (ACCUM) { float2 o = *reinterpret_cast<float2*>(Cp); a0 += o.x; a1 += o.y; }
                    *reinterpret_cast<float2*>(Cp) = make_float2(a0, a1);
                    if (OUT == 2) { v0 = a0; v1 = a1; }
                }
                if (OUT >= 1) {
                    size_t idx;
                    if (OUT == 3) {
                        int bb = bz >> 4, hh = bz & 15;
                        idx = (((size_t)(bb * kS + r)) << 10) + (hh << 6) + col;
                    } else {
                        idx = (size_t)bz * sC + (size_t)r * ldc + col;
                    }
                    __half h0, l0, h1, l1;
                    split2(v0, &h0, &l0);
                    split2(v1, &h1, &l1);
                    *reinterpret_cast<__half2*>(Ch + idx) = __halves2half2(h0, h1);
                    *reinterpret_cast<__half2*>(Cl + idx) = __halves2half2(l0, l1);
                }
            }
        }
    }
}

// ------------------------- elementwise kernels -------------------------
__global__ void embed_k(const int* __restrict__ tok, const float* __restrict__ tab,
                        float* __restrict__ out, __half* __restrict__ eh, __half* __restrict__ el)
{
    int idx = blockIdx.x * blockDim.x + threadIdx.x;
    float v = tab[(size_t)tok[idx >> 10] * kE + (idx & 1023)];
    out[idx] = v; split2(v, eh + idx, el + idx);
}

__global__ void costab_k(float* __restrict__ ct, float* __restrict__ st)
{
    int idx = blockIdx.x * blockDim.x + threadIdx.x;
    int s = idx / kD, i = idx % kD;
    float theta = powf(10000.f, (-2.f / kD) * (float)(i & 31));
    ct[idx] = cosf((float)s * theta);
    st[idx] = sinf((float)s * theta) * (i < kD/2 ? -1.f : 1.f);
}

__global__ void wqkv_k(const float* __restrict__ wq, const float* __restrict__ wk,
                       const float* __restrict__ wv, __half* __restrict__ h)
{
    int idx = blockIdx.x * blockDim.x + threadIdx.x;
    int n = idx / kE, e = idx % kE;
    int seg = n >> 10, hh = (n & 1023) >> 6, k = n & 63;
    const float* w = seg == 0 ? wq : seg == 1 ? wk : wv;
    h[idx] = __float2half(w[((size_t)hh * kE + e) * kD + k]);
}

__global__ void wtr_k(const float* __restrict__ src, __half* __restrict__ dh,
                      __half* __restrict__ dl, int K, int N)
{
    __shared__ float t[32][33];
    int k0 = blockIdx.y * 32, n0 = blockIdx.x * 32;
    for (int r = threadIdx.y; r < 32; r += 8)
        t[r][threadIdx.x] = src[(size_t)(k0 + r) * N + n0 + threadIdx.x];
    __syncthreads();
    for (int r = threadIdx.y; r < 32; r += 8) {
        size_t o = (size_t)(n0 + r) * K + k0 + threadIdx.x;
        float v = t[threadIdx.x][r];
        if (dl) split2(v, dh + o, dl + o);
        else    dh[o] = __float2half(v);
    }
}

__global__ void rope_k(const float* __restrict__ qkv, const float* __restrict__ ct,
                       const float* __restrict__ st,
                       __half* __restrict__ qh, __half* __restrict__ ql,
                       __half* __restrict__ kh, __half* __restrict__ kl,
                       __half* __restrict__ vth, __half* __restrict__ vtl)
{
    int idx = blockIdx.x * blockDim.x + threadIdx.x;
    int row = idx / kQKV, c = idx % kQKV;
    int b = row >> 10, s = row & 1023;
    int seg = c >> 10, h = (c & 1023) >> 6, i = c & 63;
    float x = qkv[idx];
    if (seg == 2) {
        size_t dst = ((size_t)(b * kH + h) * kD + i) * kS + s;
        split2(x, vth + dst, vtl + dst);
        return;
    }
    float sw = qkv[(size_t)row * kQKV + (seg << 10) + (h << 6) + ((i + 32) & 63)];
    float val = ct[(s << 6) + i] * x + st[(s << 6) + i] * sw;
    size_t dst = ((size_t)(b * kH + h) * kS + s) * kD + i;
    if (seg == 0) split2(val, qh + dst, ql + dst);
    else          split2(val, kh + dst, kl + dst);
}

__global__ void softmax_k(const float* __restrict__ sc,
                          __half* __restrict__ ph, __half* __restrict__ pl)
{
    const int r = blockIdx.x, s = r & (kS - 1), n = s + 1, t = threadIdx.x;
    const int kend = ((s >> 7) + 1) << 7;
    const float* row = sc + (size_t)r * kS;
    __half* prh = ph + (size_t)r * kS;
    __half* prl = pl + (size_t)r * kS;
    __shared__ float red[256];

    float v[4];
#pragma unroll
    for (int j = 0; j < 4; j++) {
        int i = t + j * 256;
        v[j] = (i < n) ? row[i] : -INFINITY;
    }
    float m = fmaxf(fmaxf(v[0], v[1]), fmaxf(v[2], v[3]));
    red[t] = m; __syncthreads();
    for (int o = 128; o > 0; o >>= 1) { if (t < o) red[t] = fmaxf(red[t], red[t+o]); __syncthreads(); }
    m = red[0]; __syncthreads();

    float e[4], sum = 0.f;
#pragma unroll
    for (int j = 0; j < 4; j++) {
        int i = t + j * 256;
        e[j] = (i < n) ? expf(v[j] - m) : 0.f;
        sum += e[j];
    }
    red[t] = sum; __syncthreads();
    for (int o = 128; o > 0; o >>= 1) { if (t < o) red[t] += red[t+o]; __syncthreads(); }
    float inv = 1.f / red[0];
#pragma unroll
    for (int j = 0; j < 4; j++) {
        int i = t + j * 256;
        if (i < kend) split2(e[j] * inv, prh + i, prl + i);
    }
}

__global__ void rmsnorm_k(const float* __restrict__ x, const float* __restrict__ w,
                          __half* __restrict__ yh, __half* __restrict__ yl)
{
    const int r = blockIdx.x, t = threadIdx.x;
    const float* xr = x + (size_t)r * kE;
    __shared__ float red[256];
    float sum = 0.f;
    for (int i = t; i < kE; i += 256) { float v = xr[i]; sum += v * v; }
    red[t] = sum; __syncthreads();
    for (int o = 128; o > 0; o >>= 1) { if (t < o) red[t] += red[t+o]; __syncthreads(); }
    float rs = rsqrtf(red[0] / kE + 1.1920929e-7f);
    for (int i = t; i < kE; i += 256) {
        size_t o = (size_t)r * kE + i;
        split2(xr[i] * rs * w[i], yh + o, yl + o);
    }
}

// fused ug buffer [kBS, 2F]: u = cols[0,F), g = cols[F,2F)
__global__ void elumul_k(const __half* __restrict__ ugh, const __half* __restrict__ ugl,
                         __half* __restrict__ uh, __half* __restrict__ ul)
{
    int i = blockIdx.x * blockDim.x + threadIdx.x;   // kBS*kF
    int row = i >> 12, c = i & (kF - 1);
    size_t ui = ((size_t)row << 13) + c;
    size_t gi = ui + kF;
    float u = __half2float(ugh[ui]) + __half2float(ugl[ui]) * (1.f/1024.f);
    float g = __half2float(ugh[gi]) + __half2float(ugl[gi]) * (1.f/1024.f);
    float e = g > 0.f ? g : expm1f(g);
    split2(u * e, uh + i, ul + i);
}

// ------------------------- host launcher -------------------------
#define SYM(p, s) cudaGetSymbolAddress((void**)&p, s)

extern "C" void kernel_launch(void* const* d_in, const int* in_sizes, int n_in,
                              void* d_out, int out_size)
{
    (void)in_sizes; (void)n_in; (void)out_size;
    const int*   tokens = (const int*)  d_in[0];
    const float* table = (const float*)d_in[1];
    const float *Wq = (const float*)d_in[2], *Wk = (const float*)d_in[3], *Wv = (const float*)d_in[4];
    const float *Wproj = (const float*)d_in[5], *normw = (const float*)d_in[6];
    const float *Wup = (const float*)d_in[7], *Wgate = (const float*)d_in[8], *Wdown = (const float*)d_in[9];
    const float *predW = (const float*)d_in[10], *predB = (const float*)d_in[11];
    float* logits = (float*)d_out;

    float *emb, *qkv, *sc, *ct, *st;
    __half *eh, *el, *qh, *ql, *kh, *kl, *vth, *vtl, *ph, *pl;
    __half *o2h, *o2l, *hh, *hl, *ug0h, *ug0l, *uh, *ul;
    __half *wqkvh, *wph, *wpl, *wugh, *wdh, *pwh;
    SYM(emb, g_emb); SYM(qkv, g_qkv); SYM(sc, g_sc); SYM(ct, g_ct); SYM(st, g_st);
    SYM(eh, g_eh); SYM(el, g_el);
    SYM(qh, g_qh); SYM(ql, g_ql); SYM(kh, g_kh); SYM(kl, g_kl);
    SYM(vth, g_vth); SYM(vtl, g_vtl); SYM(ph, g_ph); SYM(pl, g_pl);
    SYM(o2h, g_o2h); SYM(o2l, g_o2l); SYM(hh, g_hh); SYM(hl, g_hl);
    SYM(ug0h, g_ug0h); SYM(ug0l, g_ug0l); SYM(uh, g_uh); SYM(ul, g_ul);
    SYM(wqkvh, g_wqkvh); SYM(wph, g_wph); SYM(wpl, g_wpl);
    SYM(wugh, g_wugh); SYM(wdh, g_wdh); SYM(pwh, g_pwh);

    const int SMS128 = 2 * 2 * (128 * 176 + 128 * 176);
    const int SMS64  = 2 * 2 * (128 * 176 + 64 * 176);
    const int SM1128 = 2 * (2 * 128 * 176 + 128 * 176);
    const int SMU128 = 2 * (128 * 176 + 128 * 176);
    cudaFuncSetAttribute(tgemm_k<128,1,0,false,false,false,false>, cudaFuncAttributeMaxDynamicSharedMemorySize, SM1128);
    cudaFuncSetAttribute(tgemm_k<128,2,0,false,false,true ,false>, cudaFuncAttributeMaxDynamicSharedMemorySize, SMS128);
    cudaFuncSetAttribute(tgemm_k<128,2,0,true ,false,false,false>, cudaFuncAttributeMaxDynamicSharedMemorySize, SMS128);
    cudaFuncSetAttribute(tgemm_k<64 ,2,3,false,false,false,true >, cudaFuncAttributeMaxDynamicSharedMemorySize, SMS64);
    cudaFuncSetAttribute(tgemm_k<128,1,1,false,false,false,false>, cudaFuncAttributeMaxDynamicSharedMemorySize, SM1128);
    cudaFuncSetAttribute(tgemm_k<128,1,2,true ,false,false,false>, cudaFuncAttributeMaxDynamicSharedMemorySize, SM1128);
    cudaFuncSetAttribute(tgemm_k<128,0,0,false,true ,false,false>, cudaFuncAttributeMaxDynamicSharedMemorySize, SMU128);

    cudaStream_t s2 = g_aux.s2;
    cudaEventRecord(g_aux.fork, 0);
    cudaStreamWaitEvent(s2, g_aux.fork, 0);

    // ---- weight prep on s2 (fine-grained events) ----
    for (int l = 0; l < 4; l++) {
        const float* wq = Wq    + (size_t)l * kH * kE * kD;
        const float* wk = Wk    + (size_t)l * kH * kE * kD;
        const float* wv = Wv    + (size_t)l * kH * kE * kD;
        const float* wp = Wproj + (size_t)l * kE * kE;
        const float* wu = Wup   + (size_t)l * kE * kF;
        const float* wg = Wgate + (size_t)l * kE * kF;
        const float* wd = Wdown + (size_t)l * kF * kE;
        wqkv_k<<<kQKV * kE / 256, 256, 0, s2>>>(wq, wk, wv, wqkvh + (size_t)l*kQKV*kE);
        cudaEventRecord(g_aux.eq[l], s2);
        wtr_k<<<dim3(kE/32, kE/32), dim3(32,8), 0, s2>>>(wp, wph + (size_t)l*kE*kE, wpl + (size_t)l*kE*kE, kE, kE);
        wtr_k<<<dim3(kF/32, kE/32), dim3(32,8), 0, s2>>>(wu, wugh + (size_t)l*kF2*kE, nullptr, kE, kF);
        wtr_k<<<dim3(kF/32, kE/32), dim3(32,8), 0, s2>>>(wg, wugh + (size_t)l*kF2*kE + (size_t)kF*kE, nullptr, kE, kF);
        wtr_k<<<dim3(kE/32, kF/32), dim3(32,8), 0, s2>>>(wd, wdh + (size_t)l*kE*kF, nullptr, kF, kE);
        cudaEventRecord(g_aux.er[l], s2);
    }
    wtr_k<<<dim3(kV/32, kE/32), dim3(32,8), 0, s2>>>(predW, pwh, nullptr, kE, kV);
    cudaEventRecord(g_aux.wlog, s2);

    // ---- main compute ----
    embed_k <<<kBS * kE / 256, 256>>>(tokens, table, emb, eh, el);
    costab_k<<<kS * kD / 256, 256>>>(ct, st);

    for (int l = 0; l < 4; l++) {
        const float* nw = normw + (size_t)l * kE;
        __half* lwqkv = wqkvh + (size_t)l*kQKV*kE;
        __half* lwph  = wph  + (size_t)l*kE*kE;
        __half* lwpl  = wpl  + (size_t)l*kE*kE;
        __half* lwug  = wugh + (size_t)l*kF2*kE;
        __half* lwdh  = wdh  + (size_t)l*kE*kF;

        cudaStreamWaitEvent(0, g_aux.eq[l], 0);
        // QKV one-sided
        tgemm_k<128,1,0,false,false,false,false><<<dim3(kQKV/128, kBS/128), 512, SM1128>>>(
            eh, el, kE, 0, lwqkv, nullptr, kE, 0, qkv, nullptr, nullptr, kQKV, 0, nullptr, 1.f, kE);
        rope_k<<<kBS * kQKV / 256, 256>>>(qkv, ct, st, qh, ql, kh, kl, vth, vtl);

        // scores (full split, causal tile-skip)
        tgemm_k<128,2,0,false,false,true,false><<<dim3(kS/128, kS/128, kBH), 512, SMS128>>>(
            qh, ql, kD, (long long)kS*kD, kh, kl, kD, (long long)kS*kD,
            sc, nullptr, nullptr, kS, (long long)kS*kS, nullptr, 0.125f, kD);
        softmax_k<<<kBH * kS, 256>>>(sc, ph, pl);

        // o = P @ V (full split, causal K-bound) -> o2h/o2l
        tgemm_k<64,2,3,false,false,false,true><<<dim3(1, kS/128, kBH), 512, SMS64>>>(
            ph, pl, kS, (long long)kS*kS, vth, vtl, kS, (long long)kD*kS,
            nullptr, o2h, o2l, kD, (long long)kS*kD, nullptr, 1.f, kS);

        cudaStreamWaitEvent(0, g_aux.er[l], 0);
        // emb += o2 @ Wproj (full split)
        tgemm_k<128,2,0,true,false,false,false><<<dim3(kE/128, kBS/128), 512, SMS128>>>(
            o2h, o2l, kE, 0, lwph, lwpl, kE, 0, emb, nullptr, nullptr, kE, 0, nullptr, 1.f, kE);

        // MLP: merged up|gate (one-sided), elumul, down (one-sided, emits eh/el)
        rmsnorm_k<<<kBS, 256>>>(emb, nw, hh, hl);
        tgemm_k<128,1,1,false,false,false,false><<<dim3(kF2/128, kBS/128), 512, SM1128>>>(
            hh, hl, kE, 0, lwug, nullptr, kE, 0, nullptr, ug0h, ug0l, kF2, 0, nullptr, 1.f, kE);
        elumul_k<<<kBS * kF / 256, 256>>>(ug0h, ug0l, uh, ul);
        tgemm_k<128,1,2,true,false,false,false><<<dim3(kE/128, kBS/128), 512, SM1128>>>(
            uh, ul, kF, 0, lwdh, nullptr, kF, 0, emb, eh, el, kE, 0, nullptr, 1.f, kF);
    }

    // logits (unsplit fp16)
    cudaStreamWaitEvent(0, g_aux.wlog, 0);
    tgemm_k<128,0,0,false,true,false,false><<<dim3(kV/128, kBS/128), 512, SMU128>>>(
        eh, nullptr, kE, 0, pwh, nullptr, kE, 0, logits, nullptr, nullptr, kV, 0, predB, 1.f, kE);
}

// round 17
// speedup vs baseline: 1.2052x; 1.1154x over previous
#include <cuda_runtime.h>
#include <cuda_fp16.h>
#include <math.h>
#include <stdint.h>

namespace {
constexpr int kB = 2, kS = 1024, kE = 1024, kH = 16, kD = 64, kF = 4096, kV = 32000;
constexpr int kBS = kB * kS, kBH = kB * kH, kQKV = 3 * kE, kF2 = 2 * kF;
}

// ------------------------- device scratch -------------------------
__device__ float  g_emb [kBS * kE];
__device__ float  g_qkv [kBS * kQKV];
__device__ float  g_ct  [kS * kD];
__device__ float  g_st  [kS * kD];

__device__ __half g_eh[kBS*kE], g_el[kBS*kE];
__device__ __half g_qh[kBH*kS*kD], g_ql[kBH*kS*kD];
__device__ __half g_kh[kBH*kS*kD], g_kl[kBH*kS*kD];
__device__ __half g_vth[kBH*kD*kS], g_vtl[kBH*kD*kS];
__device__ __half g_o2h[kBS*kE], g_o2l[kBS*kE];
__device__ __half g_hh[kBS*kE],  g_hl[kBS*kE];
__device__ __half g_ug0h[(size_t)kBS*kF2], g_ug0l[(size_t)kBS*kF2];
__device__ __half g_uh[kBS*kF],  g_ul[kBS*kF];

__device__ __half g_wqkvh[4*(size_t)kQKV*kE];
__device__ __half g_wph[4*(size_t)kE*kE], g_wpl[4*(size_t)kE*kE];
__device__ __half g_wugh[4*(size_t)kF2*kE];
__device__ __half g_wdh[4*(size_t)kE*kF];
__device__ __half g_pwh[(size_t)kV*kE];

// ------------------------- stream/event plumbing -------------------------
struct Aux {
    cudaStream_t s2;
    cudaEvent_t fork, eq[4], er[4], wlog;
    Aux() {
        cudaStreamCreateWithFlags(&s2, cudaStreamNonBlocking);
        cudaEventCreateWithFlags(&fork, cudaEventDisableTiming);
        for (int i = 0; i < 4; i++) {
            cudaEventCreateWithFlags(&eq[i], cudaEventDisableTiming);
            cudaEventCreateWithFlags(&er[i], cudaEventDisableTiming);
        }
        cudaEventCreateWithFlags(&wlog, cudaEventDisableTiming);
    }
};
static Aux g_aux;

// ------------------------- PTX helpers -------------------------
__device__ __forceinline__ uint32_t smem_u32(const void* p) {
    uint32_t a;
    asm("{ .reg .u64 t; cvta.to.shared.u64 t, %1; cvt.u32.u64 %0, t; }" : "=r"(a) : "l"(p));
    return a;
}
__device__ __forceinline__ void cpasync16(uint32_t dst, const void* src) {
    asm volatile("cp.async.cg.shared.global [%0], [%1], 16;" :: "r"(dst), "l"(src));
}
#define CP_COMMIT() asm volatile("cp.async.commit_group;" ::: "memory")
#define CP_WAIT0()  asm volatile("cp.async.wait_group 0;" ::: "memory")

__device__ __forceinline__ void ldsm4(uint32_t* r, uint32_t addr) {
    asm volatile("ldmatrix.sync.aligned.m8n8.x4.shared.b16 {%0,%1,%2,%3}, [%4];"
        : "=r"(r[0]), "=r"(r[1]), "=r"(r[2]), "=r"(r[3]) : "r"(addr));
}
__device__ __forceinline__ void hmma(float* c, const uint32_t* a, const uint32_t* b) {
    asm volatile("mma.sync.aligned.m16n8k16.row.col.f32.f16.f16.f32 "
        "{%0,%1,%2,%3}, {%4,%5,%6,%7}, {%8,%9}, {%0,%1,%2,%3};"
        : "+f"(c[0]), "+f"(c[1]), "+f"(c[2]), "+f"(c[3])
        : "r"(a[0]), "r"(a[1]), "r"(a[2]), "r"(a[3]), "r"(b[0]), "r"(b[1]));
}
__device__ __forceinline__ void hmma16(uint32_t* c, const uint32_t* a, const uint32_t* b) {
    asm volatile("mma.sync.aligned.m16n8k16.row.col.f16.f16.f16.f16 "
        "{%0,%1}, {%2,%3,%4,%5}, {%6,%7}, {%0,%1};"
        : "+r"(c[0]), "+r"(c[1])
        : "r"(a[0]), "r"(a[1]), "r"(a[2]), "r"(a[3]), "r"(b[0]), "r"(b[1]));
}
__device__ __forceinline__ void split2(float v, __half* h, __half* l) {
    __half hi = __float2half(v);
    *h = hi;
    *l = __float2half((v - __half2float(hi)) * 1024.f);
}
__device__ __forceinline__ void split_pack(float a, float b, uint32_t& h, uint32_t& l) {
    __half ha = __float2half(a), hb = __float2half(b);
    __half la = __float2half((a - __half2float(ha)) * 1024.f);
    __half lb = __float2half((b - __half2float(hb)) * 1024.f);
    h = __half2_raw(__halves2half2(ha, hb)).x | ((uint32_t)__half2_raw(__halves2half2(ha, hb)).y << 16);
    __half2 hh2 = __halves2half2(ha, hb), ll2 = __halves2half2(la, lb);
    h = *reinterpret_cast<uint32_t*>(&hh2);
    l = *reinterpret_cast<uint32_t*>(&ll2);
}

template<int ROWS, int TPB>
__device__ __forceinline__ void stage_cp(uint32_t dst, const __half* __restrict__ src,
                                         long long ld, int k0, int tid)
{
#pragma unroll
    for (int it = 0; it < ROWS * 8 / TPB; it++) {
        int i = it * TPB + tid;
        int r = i >> 3, c = i & 7;
        cpasync16(dst + r * 176 + c * 16, src + (long long)r * ld + k0 + c * 8);
    }
}

// ------------------------- HMMA GEMM (512 thr, 4x4 warps) -------------------
template<int BN, int MODE, int OUT, bool ACCUM, bool BIAS>
__global__ void __launch_bounds__(512, 1)
tgemm_k(const __half* __restrict__ Ah, const __half* __restrict__ Al, int lda, long long sA,
        const __half* __restrict__ Bh, const __half* __restrict__ Bl, int ldb, long long sB,
        float* __restrict__ C, __half* __restrict__ Ch, __half* __restrict__ Cl,
        int ldc, long long sC,
        const float* __restrict__ bias, float alpha, int K)
{
    constexpr int BM = 128, BK = 64, TPB = 512;
    constexpr int WM = 4, WN = 4;
    constexpr int MT = BM / (WM * 16);
    constexpr int NT = BN / (WN * 8);
    constexpr int TILEA = BM * 176, TILEB = BN * 176;
    constexpr int NA = (MODE >= 1) ? 2 : 1;
    constexpr int NB = (MODE == 2) ? 2 : 1;
    constexpr int STAGE = NA * TILEA + NB * TILEB;

    const int bx = blockIdx.x, by = blockIdx.y, bz = blockIdx.z;
    const int NC = K / BK;

    extern __shared__ char sm[];
    const uint32_t sb = smem_u32(sm);
    const int tid = threadIdx.x, lane = tid & 31, wid = tid >> 5;
    const int m0 = (wid / WN) * MT * 16;
    const int n0 = (wid % WN) * NT * 8;

    const __half* pAh = Ah + bz * sA + (long long)by * BM * lda;
    const __half* pAl = (MODE >= 1) ? Al + bz * sA + (long long)by * BM * lda : nullptr;
    const __half* pBh = Bh + bz * sB + (long long)bx * BN * ldb;
    const __half* pBl = (MODE == 2) ? Bl + bz * sB + (long long)bx * BN * ldb : nullptr;

    float    acc1[MT][NT][4];
    uint32_t acc2[MT][NT][2];
#pragma unroll
    for (int mt = 0; mt < MT; mt++)
#pragma unroll
        for (int nt = 0; nt < NT; nt++) {
#pragma unroll
            for (int i = 0; i < 4; i++) acc1[mt][nt][i] = 0.f;
            acc2[mt][nt][0] = 0u; acc2[mt][nt][1] = 0u;
        }

    auto stage_all = [&](int buf, int k0) {
        uint32_t s0 = sb + (uint32_t)buf * STAGE;
        stage_cp<BM, TPB>(s0, pAh, lda, k0, tid);
        stage_cp<BN, TPB>(s0 + NA*TILEA, pBh, ldb, k0, tid);
        if (MODE >= 1) stage_cp<BM, TPB>(s0 + TILEA, pAl, lda, k0, tid);
        if (MODE == 2) stage_cp<BN, TPB>(s0 + NA*TILEA + TILEB, pBl, ldb, k0, tid);
    };

    stage_all(0, 0); CP_COMMIT();

    for (int i = 0; i < NC; i++) {
        CP_WAIT0();
        __syncthreads();
        if (i + 1 < NC) { stage_all((i + 1) & 1, (i + 1) * BK); CP_COMMIT(); }

        const uint32_t s0 = sb + (uint32_t)(i & 1) * STAGE;
        const uint32_t aH = s0, aL = s0 + TILEA;
        const uint32_t bH = s0 + NA*TILEA, bL = s0 + NA*TILEA + TILEB;

#pragma unroll
        for (int ks = 0; ks < 4; ks++) {
            const int kc = ks * 2;
            uint32_t ah[MT][4], al[MT][4], bhf[NT][2], blf[NT][2];
#pragma unroll
            for (int nt = 0; nt < NT; nt += 2) {
                const int g = lane >> 3;
                const uint32_t off =
                    (uint32_t)(n0 + nt * 8 + ((g >> 1) << 3) + (lane & 7)) * 176
                    + (uint32_t)(kc + (g & 1)) * 16;
                uint32_t r[4];
                ldsm4(r, bH + off);
                bhf[nt][0] = r[0]; bhf[nt][1] = r[1];
                bhf[nt+1][0] = r[2]; bhf[nt+1][1] = r[3];
                if (MODE == 2) {
                    ldsm4(r, bL + off);
                    blf[nt][0] = r[0]; blf[nt][1] = r[1];
                    blf[nt+1][0] = r[2]; blf[nt+1][1] = r[3];
                }
            }
#pragma unroll
            for (int mt = 0; mt < MT; mt++) {
                const uint32_t off =
                    (uint32_t)(m0 + mt * 16 + (lane & 15)) * 176
                    + (uint32_t)(kc + (lane >> 4)) * 16;
                ldsm4(ah[mt], aH + off);
                if (MODE >= 1) ldsm4(al[mt], aL + off);
            }
#pragma unroll
            for (int mt = 0; mt < MT; mt++)
#pragma unroll
                for (int nt = 0; nt < NT; nt++) {
                    hmma(acc1[mt][nt], ah[mt], bhf[nt]);
                    if (MODE == 2) hmma16(acc2[mt][nt], ah[mt], blf[nt]);
                    if (MODE >= 1) hmma16(acc2[mt][nt], al[mt], bhf[nt]);
                }
        }
    }

    const float inv = 1.f / 1024.f;
#pragma unroll
    for (int mt = 0; mt < MT; mt++) {
#pragma unroll
        for (int nt = 0; nt < NT; nt++) {
            const int row = by * BM + m0 + mt * 16 + (lane >> 2);
            const int col = bx * BN + n0 + nt * 8 + ((lane & 3) << 1);
#pragma unroll
            for (int h = 0; h < 2; h++) {
                const int r = row + h * 8;
                float v0 = acc1[mt][nt][2*h], v1 = acc1[mt][nt][2*h+1];
                if (MODE >= 1) {
                    __half2 c2 = *reinterpret_cast<__half2*>(&acc2[mt][nt][h]);
                    v0 += __low2float(c2) * inv;
                    v1 += __high2float(c2) * inv;
                }
                v0 *= alpha; v1 *= alpha;
                if (BIAS) { v0 += bias[col]; v1 += bias[col + 1]; }
                if (OUT == 0 || OUT == 2) {
                    float* Cp = C + bz * sC + (long long)r * ldc + col;
                    float a0 = v0, a1 = v1;
                    if (ACCUM) { float2 o = *reinterpret_cast<float2*>(Cp); a0 += o.x; a1 += o.y; }
                    *reinterpret_cast<float2*>(Cp) = make_float2(a0, a1);
                    if (OUT == 2) { v0 = a0; v1 = a1; }
                }
                if (OUT >= 1) {
                    size_t idx = (size_t)bz * sC + (size_t)r * ldc + col;
                    __half h0, l0, h1, l1;
                    split2(v0, &h0, &l0);
                    split2(v1, &h1, &l1);
                    *reinterpret_cast<__half2*>(Ch + idx) = __halves2half2(h0, h1);
                    *reinterpret_cast<__half2*>(Cl + idx) = __halves2half2(l0, l1);
                }
            }
        }
    }
}

// ------------------------- fused flash attention -------------------------
// grid (8 row-tiles, 32 bh), 256 thr (8 warps x 16 rows). Full-split QK and PV,
// online softmax with deferred normalization, O written to o2h/o2l directly.
__global__ void __launch_bounds__(256, 1)
fattn_k(const __half* __restrict__ Qh, const __half* __restrict__ Ql,
        const __half* __restrict__ Kh, const __half* __restrict__ Kl,
        const __half* __restrict__ Vh, const __half* __restrict__ Vl,
        __half* __restrict__ Oh, __half* __restrict__ Ol)
{
    const int by = blockIdx.x, zbh = blockIdx.y;
    const int tid = threadIdx.x, lane = tid & 31, wid = tid >> 5;
    const int m0 = wid * 16;
    const int NTt = by + 1;

    extern __shared__ char sm[];
    const uint32_t sb = smem_u32(sm);
    const uint32_t SQH = 0, SQL = 22528, SK0 = 45056, SV0 = 135168;

    const __half* qh = Qh + (size_t)zbh * kS * kD + (size_t)by * 128 * kD;
    const __half* ql = Ql + (size_t)zbh * kS * kD + (size_t)by * 128 * kD;
    const __half* khp = Kh + (size_t)zbh * kS * kD;
    const __half* klp = Kl + (size_t)zbh * kS * kD;
    const __half* vhp = Vh + (size_t)zbh * kD * kS;
    const __half* vlp = Vl + (size_t)zbh * kD * kS;

    auto stage_kv = [&](int buf, int t) {
        uint32_t kb = sb + SK0 + buf * 45056;
        stage_cp<128, 256>(kb,         khp + (long long)t*128*kD, kD, 0, tid);
        stage_cp<128, 256>(kb + 22528, klp + (long long)t*128*kD, kD, 0, tid);
        uint32_t vb = sb + SV0 + buf * 34816;
#pragma unroll
        for (int it = 0; it < 4; it++) {
            int i = it * 256 + tid;
            int r = i >> 4, c = i & 15;
            cpasync16(vb + r * 272 + c * 16,         vhp + (long long)r * kS + t*128 + c*8);
            cpasync16(vb + 17408 + r * 272 + c * 16, vlp + (long long)r * kS + t*128 + c*8);
        }
    };

    stage_cp<128, 256>(sb + SQH, qh, kD, 0, tid);
    stage_cp<128, 256>(sb + SQL, ql, kD, 0, tid);
    stage_kv(0, 0);
    CP_COMMIT();

    float    oa1[8][4];
    uint32_t oa2[8][2];
#pragma unroll
    for (int j = 0; j < 8; j++) {
#pragma unroll
        for (int i = 0; i < 4; i++) oa1[j][i] = 0.f;
        oa2[j][0] = 0u; oa2[j][1] = 0u;
    }
    float mrow0 = -INFINITY, mrow1 = -INFINITY, lrow0 = 0.f, lrow1 = 0.f;
    uint32_t qfh[4][4], qfl[4][4];
    bool qload = false;
    const float inv1024 = 1.f / 1024.f;

    for (int t = 0; t < NTt; t++) {
        CP_WAIT0();
        __syncthreads();
        if (t + 1 < NTt) { stage_kv((t + 1) & 1, t + 1); CP_COMMIT(); }

        if (!qload) {
#pragma unroll
            for (int kk = 0; kk < 4; kk++) {
                uint32_t off = (uint32_t)(m0 + (lane & 15)) * 176 + (uint32_t)(kk*2 + (lane >> 4)) * 16;
                ldsm4(qfh[kk], sb + SQH + off);
                ldsm4(qfl[kk], sb + SQL + off);
            }
            qload = true;
        }
        const uint32_t kb = sb + SK0 + (t & 1) * 45056;
        const uint32_t vb = sb + SV0 + (t & 1) * 34816;

        float s1[16][4];
        uint32_t s2[16][2];
#pragma unroll
        for (int j = 0; j < 16; j++) {
#pragma unroll
            for (int i = 0; i < 4; i++) s1[j][i] = 0.f;
            s2[j][0] = 0u; s2[j][1] = 0u;
        }
#pragma unroll
        for (int kk = 0; kk < 4; kk++) {
            const int kc = kk * 2;
#pragma unroll
            for (int nt = 0; nt < 16; nt += 2) {
                const int g = lane >> 3;
                uint32_t off = (uint32_t)(nt*8 + ((g>>1)<<3) + (lane & 7)) * 176
                             + (uint32_t)(kc + (g & 1)) * 16;
                uint32_t rh[4], rl[4];
                ldsm4(rh, kb + off);
                ldsm4(rl, kb + 22528 + off);
                uint32_t b0[2] = {rh[0], rh[1]}, b1[2] = {rh[2], rh[3]};
                uint32_t c0[2] = {rl[0], rl[1]}, c1[2] = {rl[2], rl[3]};
                hmma(s1[nt],   qfh[kk], b0);  hmma(s1[nt+1], qfh[kk], b1);
                hmma16(s2[nt], qfh[kk], c0);  hmma16(s2[nt+1], qfh[kk], c1);
                hmma16(s2[nt], qfl[kk], b0);  hmma16(s2[nt+1], qfl[kk], b1);
            }
        }
        // combine + scale + causal mask
#pragma unroll
        for (int j = 0; j < 16; j++) {
            __half2 ca = *reinterpret_cast<__half2*>(&s2[j][0]);
            __half2 cb = *reinterpret_cast<__half2*>(&s2[j][1]);
            s1[j][0] = (s1[j][0] + __low2float(ca)  * inv1024) * 0.125f;
            s1[j][1] = (s1[j][1] + __high2float(ca) * inv1024) * 0.125f;
            s1[j][2] = (s1[j][2] + __low2float(cb)  * inv1024) * 0.125f;
            s1[j][3] = (s1[j][3] + __high2float(cb) * inv1024) * 0.125f;
        }
        if (t == by) {
            const int r0 = m0 + (lane >> 2), r1 = r0 + 8;
#pragma unroll
            for (int j = 0; j < 16; j++) {
                int c0i = j*8 + ((lane & 3) << 1), c1i = c0i + 1;
                if (c0i > r0) s1[j][0] = -INFINITY;
                if (c1i > r0) s1[j][1] = -INFINITY;
                if (c0i > r1) s1[j][2] = -INFINITY;
                if (c1i > r1) s1[j][3] = -INFINITY;
            }
        }
        // row max
        float mt0 = -INFINITY, mt1 = -INFINITY;
#pragma unroll
        for (int j = 0; j < 16; j++) {
            mt0 = fmaxf(mt0, fmaxf(s1[j][0], s1[j][1]));
            mt1 = fmaxf(mt1, fmaxf(s1[j][2], s1[j][3]));
        }
        mt0 = fmaxf(mt0, __shfl_xor_sync(0xffffffff, mt0, 1));
        mt0 = fmaxf(mt0, __shfl_xor_sync(0xffffffff, mt0, 2));
        mt1 = fmaxf(mt1, __shfl_xor_sync(0xffffffff, mt1, 1));
        mt1 = fmaxf(mt1, __shfl_xor_sync(0xffffffff, mt1, 2));
        float mn0 = fmaxf(mrow0, mt0), mn1 = fmaxf(mrow1, mt1);
        float f0 = __expf(mrow0 - mn0), f1 = __expf(mrow1 - mn1);
        mrow0 = mn0; mrow1 = mn1;
        lrow0 *= f0; lrow1 *= f1;
        __half2 hf0 = __float2half2_rn(f0), hf1 = __float2half2_rn(f1);
#pragma unroll
        for (int j = 0; j < 8; j++) {
            oa1[j][0] *= f0; oa1[j][1] *= f0; oa1[j][2] *= f1; oa1[j][3] *= f1;
            __half2 a = *reinterpret_cast<__half2*>(&oa2[j][0]);
            __half2 b = *reinterpret_cast<__half2*>(&oa2[j][1]);
            a = __hmul2(a, hf0); b = __hmul2(b, hf1);
            oa2[j][0] = *reinterpret_cast<uint32_t*>(&a);
            oa2[j][1] = *reinterpret_cast<uint32_t*>(&b);
        }
        // PV per k16 group
#pragma unroll
        for (int g = 0; g < 8; g++) {
            const int j0 = 2*g, j1 = 2*g + 1;
            float e00 = __expf(s1[j0][0] - mn0), e01 = __expf(s1[j0][1] - mn0);
            float e02 = __expf(s1[j0][2] - mn1), e03 = __expf(s1[j0][3] - mn1);
            float e10 = __expf(s1[j1][0] - mn0), e11 = __expf(s1[j1][1] - mn0);
            float e12 = __expf(s1[j1][2] - mn1), e13 = __expf(s1[j1][3] - mn1);
            lrow0 += e00 + e01 + e10 + e11;
            lrow1 += e02 + e03 + e12 + e13;
            uint32_t ah[4], al[4];
            split_pack(e00, e01, ah[0], al[0]);
            split_pack(e02, e03, ah[1], al[1]);
            split_pack(e10, e11, ah[2], al[2]);
            split_pack(e12, e13, ah[3], al[3]);
#pragma unroll
            for (int nt = 0; nt < 8; nt += 2) {
                const int gg = lane >> 3;
                uint32_t off = (uint32_t)(nt*8 + ((gg>>1)<<3) + (lane & 7)) * 272
                             + (uint32_t)(g*2 + (gg & 1)) * 16;
                uint32_t rh[4], rl[4];
                ldsm4(rh, vb + off);
                ldsm4(rl, vb + 17408 + off);
                uint32_t b0[2] = {rh[0], rh[1]}, b1[2] = {rh[2], rh[3]};
                uint32_t c0[2] = {rl[0], rl[1]}, c1[2] = {rl[2], rl[3]};
                hmma(oa1[nt],   ah, b0);  hmma(oa1[nt+1], ah, b1);
                hmma16(oa2[nt], ah, c0);  hmma16(oa2[nt+1], ah, c1);
                hmma16(oa2[nt], al, b0);  hmma16(oa2[nt+1], al, b1);
            }
        }
    }
    // reduce l over the 4 lanes of each row, write O
    lrow0 += __shfl_xor_sync(0xffffffff, lrow0, 1);
    lrow0 += __shfl_xor_sync(0xffffffff, lrow0, 2);
    lrow1 += __shfl_xor_sync(0xffffffff, lrow1, 1);
    lrow1 += __shfl_xor_sync(0xffffffff, lrow1, 2);
    const float il0 = 1.f / lrow0, il1 = 1.f / lrow1;
    const int b = zbh >> 4, hd = zbh & 15;
    const int r0 = by*128 + m0 + (lane >> 2);
#pragma unroll
    for (int j = 0; j < 8; j++) {
        const int col = j*8 + ((lane & 3) << 1);
        __half2 a = *reinterpret_cast<__half2*>(&oa2[j][0]);
        __half2 c = *reinterpret_cast<__half2*>(&oa2[j][1]);
        float v0 = (oa1[j][0] + __low2float(a)  * inv1024) * il0;
        float v1 = (oa1[j][1] + __high2float(a) * inv1024) * il0;
        float v2 = (oa1[j][2] + __low2float(c)  * inv1024) * il1;
        float v3 = (oa1[j][3] + __high2float(c) * inv1024) * il1;
        size_t i0 = (((size_t)(b * kS + r0)) << 10) + (hd << 6) + col;
        size_t i1 = (((size_t)(b * kS + r0 + 8)) << 10) + (hd << 6) + col;
        __half h0, l0, h1, l1;
        split2(v0, &h0, &l0); split2(v1, &h1, &l1);
        *reinterpret_cast<__half2*>(Oh + i0) = __halves2half2(h0, h1);
        *reinterpret_cast<__half2*>(Ol + i0) = __halves2half2(l0, l1);
        split2(v2, &h0, &l0); split2(v3, &h1, &l1);
        *reinterpret_cast<__half2*>(Oh + i1) = __halves2half2(h0, h1);
        *reinterpret_cast<__half2*>(Ol + i1) = __halves2half2(l0, l1);
    }
}

// ------------------------- elementwise kernels -------------------------
__global__ void embed_k(const int* __restrict__ tok, const float* __restrict__ tab,
                        float* __restrict__ out, __half* __restrict__ eh, __half* __restrict__ el)
{
    int idx = blockIdx.x * blockDim.x + threadIdx.x;
    float v = tab[(size_t)tok[idx >> 10] * kE + (idx & 1023)];
    out[idx] = v; split2(v, eh + idx, el + idx);
}

__global__ void costab_k(float* __restrict__ ct, float* __restrict__ st)
{
    int idx = blockIdx.x * blockDim.x + threadIdx.x;
    int s = idx / kD, i = idx % kD;
    float theta = powf(10000.f, (-2.f / kD) * (float)(i & 31));
    ct[idx] = cosf((float)s * theta);
    st[idx] = sinf((float)s * theta) * (i < kD/2 ? -1.f : 1.f);
}

__global__ void wqkv_k(const float* __restrict__ wq, const float* __restrict__ wk,
                       const float* __restrict__ wv, __half* __restrict__ h)
{
    int idx = blockIdx.x * blockDim.x + threadIdx.x;
    int n = idx / kE, e = idx % kE;
    int seg = n >> 10, hh = (n & 1023) >> 6, k = n & 63;
    const float* w = seg == 0 ? wq : seg == 1 ? wk : wv;
    h[idx] = __float2half(w[((size_t)hh * kE + e) * kD + k]);
}

__global__ void wtr_k(const float* __restrict__ src, __half* __restrict__ dh,
                      __half* __restrict__ dl, int K, int N)
{
    __shared__ float t[32][33];
    int k0 = blockIdx.y * 32, n0 = blockIdx.x * 32;
    for (int r = threadIdx.y; r < 32; r += 8)
        t[r][threadIdx.x] = src[(size_t)(k0 + r) * N + n0 + threadIdx.x];
    __syncthreads();
    for (int r = threadIdx.y; r < 32; r += 8) {
        size_t o = (size_t)(n0 + r) * K + k0 + threadIdx.x;
        float v = t[threadIdx.x][r];
        if (dl) split2(v, dh + o, dl + o);
        else    dh[o] = __float2half(v);
    }
}

__global__ void rope_k(const float* __restrict__ qkv, const float* __restrict__ ct,
                       const float* __restrict__ st,
                       __half* __restrict__ qh, __half* __restrict__ ql,
                       __half* __restrict__ kh, __half* __restrict__ kl,
                       __half* __restrict__ vth, __half* __restrict__ vtl)
{
    int idx = blockIdx.x * blockDim.x + threadIdx.x;
    int row = idx / kQKV, c = idx % kQKV;
    int b = row >> 10, s = row & 1023;
    int seg = c >> 10, h = (c & 1023) >> 6, i = c & 63;
    float x = qkv[idx];
    if (seg == 2) {
        size_t dst = ((size_t)(b * kH + h) * kD + i) * kS + s;
        split2(x, vth + dst, vtl + dst);
        return;
    }
    float sw = qkv[(size_t)row * kQKV + (seg << 10) + (h << 6) + ((i + 32) & 63)];
    float val = ct[(s << 6) + i] * x + st[(s << 6) + i] * sw;
    size_t dst = ((size_t)(b * kH + h) * kS + s) * kD + i;
    if (seg == 0) split2(val, qh + dst, ql + dst);
    else          split2(val, kh + dst, kl + dst);
}

__global__ void rmsnorm_k(const float* __restrict__ x, const float* __restrict__ w,
                          __half* __restrict__ yh, __half* __restrict__ yl)
{
    const int r = blockIdx.x, t = threadIdx.x;
    const float* xr = x + (size_t)r * kE;
    __shared__ float red[256];
    float sum = 0.f;
    for (int i = t; i < kE; i += 256) { float v = xr[i]; sum += v * v; }
    red[t] = sum; __syncthreads();
    for (int o = 128; o > 0; o >>= 1) { if (t < o) red[t] += red[t+o]; __syncthreads(); }
    float rs = rsqrtf(red[0] / kE + 1.1920929e-7f);
    for (int i = t; i < kE; i += 256) {
        size_t o = (size_t)r * kE + i;
        split2(xr[i] * rs * w[i], yh + o, yl + o);
    }
}

__global__ void elumul_k(const __half* __restrict__ ugh, const __half* __restrict__ ugl,
                         __half* __restrict__ uh, __half* __restrict__ ul)
{
    int i = blockIdx.x * blockDim.x + threadIdx.x;
    int row = i >> 12, c = i & (kF - 1);
    size_t ui = ((size_t)row << 13) + c;
    size_t gi = ui + kF;
    float u = __half2float(ugh[ui]) + __half2float(ugl[ui]) * (1.f/1024.f);
    float g = __half2float(ugh[gi]) + __half2float(ugl[gi]) * (1.f/1024.f);
    float e = g > 0.f ? g : expm1f(g);
    split2(u * e, uh + i, ul + i);
}

// ------------------------- host launcher -------------------------
#define SYM(p, s) cudaGetSymbolAddress((void**)&p, s)

extern "C" void kernel_launch(void* const* d_in, const int* in_sizes, int n_in,
                              void* d_out, int out_size)
{
    (void)in_sizes; (void)n_in; (void)out_size;
    const int*   tokens = (const int*)  d_in[0];
    const float* table = (const float*)d_in[1];
    const float *Wq = (const float*)d_in[2], *Wk = (const float*)d_in[3], *Wv = (const float*)d_in[4];
    const float *Wproj = (const float*)d_in[5], *normw = (const float*)d_in[6];
    const float *Wup = (const float*)d_in[7], *Wgate = (const float*)d_in[8], *Wdown = (const float*)d_in[9];
    const float *predW = (const float*)d_in[10], *predB = (const float*)d_in[11];
    float* logits = (float*)d_out;

    float *emb, *qkv, *ct, *st;
    __half *eh, *el, *qh, *ql, *kh, *kl, *vth, *vtl;
    __half *o2h, *o2l, *hh, *hl, *ug0h, *ug0l, *uh, *ul;
    __half *wqkvh, *wph, *wpl, *wugh, *wdh, *pwh;
    SYM(emb, g_emb); SYM(qkv, g_qkv); SYM(ct, g_ct); SYM(st, g_st);
    SYM(eh, g_eh); SYM(el, g_el);
    SYM(qh, g_qh); SYM(ql, g_ql); SYM(kh, g_kh); SYM(kl, g_kl);
    SYM(vth, g_vth); SYM(vtl, g_vtl);
    SYM(o2h, g_o2h); SYM(o2l, g_o2l); SYM(hh, g_hh); SYM(hl, g_hl);
    SYM(ug0h, g_ug0h); SYM(ug0l, g_ug0l); SYM(uh, g_uh); SYM(ul, g_ul);
    SYM(wqkvh, g_wqkvh); SYM(wph, g_wph); SYM(wpl, g_wpl);
    SYM(wugh, g_wugh); SYM(wdh, g_wdh); SYM(pwh, g_pwh);

    const int SMS128 = 2 * 2 * (128 * 176 + 128 * 176);
    const int SM1128 = 2 * (2 * 128 * 176 + 128 * 176);
    const int SMU128 = 2 * (128 * 176 + 128 * 176);
    const int SMFA   = 204800;
    cudaFuncSetAttribute(tgemm_k<128,1,0,false,false>, cudaFuncAttributeMaxDynamicSharedMemorySize, SM1128);
    cudaFuncSetAttribute(tgemm_k<128,2,0,true ,false>, cudaFuncAttributeMaxDynamicSharedMemorySize, SMS128);
    cudaFuncSetAttribute(tgemm_k<128,1,1,false,false>, cudaFuncAttributeMaxDynamicSharedMemorySize, SM1128);
    cudaFuncSetAttribute(tgemm_k<128,1,2,true ,false>, cudaFuncAttributeMaxDynamicSharedMemorySize, SM1128);
    cudaFuncSetAttribute(tgemm_k<128,0,0,false,true >, cudaFuncAttributeMaxDynamicSharedMemorySize, SMU128);
    cudaFuncSetAttribute(fattn_k, cudaFuncAttributeMaxDynamicSharedMemorySize, SMFA);

    cudaStream_t s2 = g_aux.s2;
    cudaEventRecord(g_aux.fork, 0);
    cudaStreamWaitEvent(s2, g_aux.fork, 0);

    for (int l = 0; l < 4; l++) {
        const float* wq = Wq    + (size_t)l * kH * kE * kD;
        const float* wk = Wk    + (size_t)l * kH * kE * kD;
        const float* wv = Wv    + (size_t)l * kH * kE * kD;
        const float* wp = Wproj + (size_t)l * kE * kE;
        const float* wu = Wup   + (size_t)l * kE * kF;
        const float* wg = Wgate + (size_t)l * kE * kF;
        const float* wd = Wdown + (size_t)l * kF * kE;
        wqkv_k<<<kQKV * kE / 256, 256, 0, s2>>>(wq, wk, wv, wqkvh + (size_t)l*kQKV*kE);
        cudaEventRecord(g_aux.eq[l], s2);
        wtr_k<<<dim3(kE/32, kE/32), dim3(32,8), 0, s2>>>(wp, wph + (size_t)l*kE*kE, wpl + (size_t)l*kE*kE, kE, kE);
        wtr_k<<<dim3(kF/32, kE/32), dim3(32,8), 0, s2>>>(wu, wugh + (size_t)l*kF2*kE, nullptr, kE, kF);
        wtr_k<<<dim3(kF/32, kE/32), dim3(32,8), 0, s2>>>(wg, wugh + (size_t)l*kF2*kE + (size_t)kF*kE, nullptr, kE, kF);
        wtr_k<<<dim3(kE/32, kF/32), dim3(32,8), 0, s2>>>(wd, wdh + (size_t)l*kE*kF, nullptr, kF, kE);
        cudaEventRecord(g_aux.er[l], s2);
    }
    wtr_k<<<dim3(kV/32, kE/32), dim3(32,8), 0, s2>>>(predW, pwh, nullptr, kE, kV);
    cudaEventRecord(g_aux.wlog, s2);

    embed_k <<<kBS * kE / 256, 256>>>(tokens, table, emb, eh, el);
    costab_k<<<kS * kD / 256, 256>>>(ct, st);

    for (int l = 0; l < 4; l++) {
        const float* nw = normw + (size_t)l * kE;
        __half* lwqkv = wqkvh + (size_t)l*kQKV*kE;
        __half* lwph  = wph  + (size_t)l*kE*kE;
        __half* lwpl  = wpl  + (size_t)l*kE*kE;
        __half* lwug  = wugh + (size_t)l*kF2*kE;
        __half* lwdh  = wdh  + (size_t)l*kE*kF;

        cudaStreamWaitEvent(0, g_aux.eq[l], 0);
        tgemm_k<128,1,0,false,false><<<dim3(kQKV/128, kBS/128), 512, SM1128>>>(
            eh, el, kE, 0, lwqkv, nullptr, kE, 0, qkv, nullptr, nullptr, kQKV, 0, nullptr, 1.f, kE);
        rope_k<<<kBS * kQKV / 256, 256>>>(qkv, ct, st, qh, ql, kh, kl, vth, vtl);

        // fused attention: scores + softmax + PV -> o2h/o2l
        fattn_k<<<dim3(kS/128, kBH), 256, SMFA>>>(qh, ql, kh, kl, vth, vtl, o2h, o2l);

        cudaStreamWaitEvent(0, g_aux.er[l], 0);
        tgemm_k<128,2,0,true,false><<<dim3(kE/128, kBS/128), 512, SMS128>>>(
            o2h, o2l, kE, 0, lwph, lwpl, kE, 0, emb, nullptr, nullptr, kE, 0, nullptr, 1.f, kE);

        rmsnorm_k<<<kBS, 256>>>(emb, nw, hh, hl);
        tgemm_k<128,1,1,false,false><<<dim3(kF2/128, kBS/128), 512, SM1128>>>(
            hh, hl, kE, 0, lwug, nullptr, kE, 0, nullptr, ug0h, ug0l, kF2, 0, nullptr, 1.f, kE);
        elumul_k<<<kBS * kF / 256, 256>>>(ug0h, ug0l, uh, ul);
        tgemm_k<128,1,2,true,false><<<dim3(kE/128, kBS/128), 512, SM1128>>>(
            uh, ul, kF, 0, lwdh, nullptr, kF, 0, emb, eh, el, kE, 0, nullptr, 1.f, kF);
    }

    cudaStreamWaitEvent(0, g_aux.wlog, 0);
    tgemm_k<128,0,0,false,true><<<dim3(kV/128, kBS/128), 512, SMU128>>>(
        eh, nullptr, kE, 0, pwh, nullptr, kE, 0, logits, nullptr, nullptr, kV, 0, predB, 1.f, kE);
}